// round 12
// baseline (speedup 1.0000x reference)
#include <cuda_runtime.h>
#include <cuda_bf16.h>
#include <math.h>
#include <stdint.h>

#define S_LEN 256
#define B_SZ  16
#define V_SZ  32000
#define E_SZ  512
#define H_SZ  1024
#define M_SZ  (S_LEN * B_SZ)   // 4096

// ---------------------------------------------------------------------------
// Device scratch (static — no runtime allocation allowed)
// ---------------------------------------------------------------------------
__device__ float    g_x [M_SZ * H_SZ];
__device__ float    g_th[M_SZ * H_SZ];
__device__ unsigned g_bar;
__device__ __align__(16) __nv_bfloat16 g_th_hi[M_SZ * H_SZ];
__device__ __align__(16) __nv_bfloat16 g_th_lo[M_SZ * H_SZ];
__device__ __align__(16) __nv_bfloat16 g_wo_hi[(size_t)V_SZ * H_SZ];
__device__ __align__(16) __nv_bfloat16 g_wo_lo[(size_t)V_SZ * H_SZ];

#define SMEM_SWIZZLE_128B(o) ((o) ^ (((o) >> 3) & 0x70))

__device__ __forceinline__ uint32_t smem_to_u32(const void* p) {
    uint32_t a;
    asm("{ .reg .u64 t; cvta.to.shared.u64 t, %1; cvt.u32.u64 %0, t; }"
        : "=r"(a) : "l"(p));
    return a;
}

__device__ __forceinline__ void cp16(uint32_t saddr, const void* g) {
    unsigned long long ga = (unsigned long long)__cvta_generic_to_global(g);
    asm volatile("cp.async.cg.shared.global [%0], [%1], 16;"
                 :: "r"(saddr), "l"(ga) : "memory");
}
__device__ __forceinline__ void cp_commit() {
    asm volatile("cp.async.commit_group;" ::: "memory");
}
template<int N>
__device__ __forceinline__ void cp_wait() {
    asm volatile("cp.async.wait_group %0;" :: "n"(N) : "memory");
}

__device__ __forceinline__ void ldsm_x4(uint32_t* r, uint32_t addr) {
    asm volatile("ldmatrix.sync.aligned.m8n8.x4.shared.b16 {%0,%1,%2,%3}, [%4];"
                 : "=r"(r[0]), "=r"(r[1]), "=r"(r[2]), "=r"(r[3]) : "r"(addr));
}
__device__ __forceinline__ void mma16816(float* d, const uint32_t* a, const uint32_t* b) {
    asm volatile(
        "mma.sync.aligned.m16n8k16.row.col.f32.bf16.bf16.f32 "
        "{%0,%1,%2,%3}, {%4,%5,%6,%7}, {%8,%9}, {%0,%1,%2,%3};"
        : "+f"(d[0]), "+f"(d[1]), "+f"(d[2]), "+f"(d[3])
        : "r"(a[0]), "r"(a[1]), "r"(a[2]), "r"(a[3]), "r"(b[0]), "r"(b[1]));
}

// ---------------------------------------------------------------------------
// Scalar NT SGEMM (f32x2) — input projection only (M=4096,N=1024,K=512)
// ---------------------------------------------------------------------------
template<bool GATHER>
__global__ void __launch_bounds__(256) sgemm128_nt(
    const float* __restrict__ A,
    const float* __restrict__ B,
    const float* __restrict__ bias,
    const int*   __restrict__ tokens,
    float* __restrict__ C,
    int N, int K)
{
    __shared__ float As[2][8][128];
    __shared__ float Bs[2][8][128];

    const int tid = threadIdx.x;
    const int bm  = blockIdx.y;
    const int bn  = blockIdx.x;

    const int lrow = tid >> 1;
    const int lk   = (tid & 1) << 2;

    const float* Arow;
    if (GATHER) {
        const int tok = tokens[bm * 128 + lrow];
        Arow = A + (size_t)tok * K;
    } else {
        Arow = A + (size_t)(bm * 128 + lrow) * K;
    }
    const float* Brow = B + (size_t)(bn * 128 + lrow) * K;

    const int tx = tid & 15;
    const int ty = tid >> 4;

    unsigned long long acc2[8][4];
#pragma unroll
    for (int i = 0; i < 8; i++)
#pragma unroll
        for (int jp = 0; jp < 4; jp++) acc2[i][jp] = 0ull;

    {
        float4 a4 = *(const float4*)(Arow + lk);
        float4 b4 = *(const float4*)(Brow + lk);
        As[0][lk + 0][lrow] = a4.x; As[0][lk + 1][lrow] = a4.y;
        As[0][lk + 2][lrow] = a4.z; As[0][lk + 3][lrow] = a4.w;
        Bs[0][lk + 0][lrow] = b4.x; Bs[0][lk + 1][lrow] = b4.y;
        Bs[0][lk + 2][lrow] = b4.z; Bs[0][lk + 3][lrow] = b4.w;
    }
    __syncthreads();

    const int nt = K >> 3;
    for (int t = 0; t < nt; ++t) {
        const int cur = t & 1;
        float4 na, nb;
        if (t + 1 < nt) {
            na = *(const float4*)(Arow + (t + 1) * 8 + lk);
            nb = *(const float4*)(Brow + (t + 1) * 8 + lk);
        }
#pragma unroll
        for (int k = 0; k < 8; k++) {
            float af[8];
            *(float4*)(af)     = *(const float4*)&As[cur][k][ty * 8];
            *(float4*)(af + 4) = *(const float4*)&As[cur][k][ty * 8 + 4];
            ulonglong2 b01 = *(const ulonglong2*)&Bs[cur][k][tx * 8];
            ulonglong2 b23 = *(const ulonglong2*)&Bs[cur][k][tx * 8 + 4];
#pragma unroll
            for (int i = 0; i < 8; i++) {
                unsigned long long ai;
                asm("mov.b64 %0, {%1, %1};" : "=l"(ai) : "f"(af[i]));
                asm("fma.rn.f32x2 %0, %1, %2, %0;" : "+l"(acc2[i][0]) : "l"(ai), "l"(b01.x));
                asm("fma.rn.f32x2 %0, %1, %2, %0;" : "+l"(acc2[i][1]) : "l"(ai), "l"(b01.y));
                asm("fma.rn.f32x2 %0, %1, %2, %0;" : "+l"(acc2[i][2]) : "l"(ai), "l"(b23.x));
                asm("fma.rn.f32x2 %0, %1, %2, %0;" : "+l"(acc2[i][3]) : "l"(ai), "l"(b23.y));
            }
        }
        if (t + 1 < nt) {
            const int nxt = cur ^ 1;
            As[nxt][lk + 0][lrow] = na.x; As[nxt][lk + 1][lrow] = na.y;
            As[nxt][lk + 2][lrow] = na.z; As[nxt][lk + 3][lrow] = na.w;
            Bs[nxt][lk + 0][lrow] = nb.x; Bs[nxt][lk + 1][lrow] = nb.y;
            Bs[nxt][lk + 2][lrow] = nb.z; Bs[nxt][lk + 3][lrow] = nb.w;
            __syncthreads();
        }
    }

    const int gm0 = bm * 128 + ty * 8;
    const int gn0 = bn * 128 + tx * 8;
    float bb[8];
    if (bias) {
        *(float4*)(bb)     = *(const float4*)(bias + gn0);
        *(float4*)(bb + 4) = *(const float4*)(bias + gn0 + 4);
    } else {
#pragma unroll
        for (int j = 0; j < 8; j++) bb[j] = 0.f;
    }
#pragma unroll
    for (int i = 0; i < 8; i++) {
        float cv[8];
#pragma unroll
        for (int jp = 0; jp < 4; jp++) {
            float lo, hi;
            asm("mov.b64 {%0, %1}, %2;" : "=f"(lo), "=f"(hi) : "l"(acc2[i][jp]));
            cv[2 * jp]     = lo + bb[2 * jp];
            cv[2 * jp + 1] = hi + bb[2 * jp + 1];
        }
        float* crow = C + (size_t)(gm0 + i) * N + gn0;
        *(float4*)(crow)     = *(float4*)(cv);
        *(float4*)(crow + 4) = *(float4*)(cv + 4);
    }
}

// ---------------------------------------------------------------------------
// hi/lo split helper
// ---------------------------------------------------------------------------
__device__ __forceinline__ void split_bf16(float x, __nv_bfloat16& hi, __nv_bfloat16& lo)
{
    hi = __float2bfloat16(x);
    lo = __float2bfloat16(x - __bfloat162float(hi));
}

// ---------------------------------------------------------------------------
// init: th[0] = tanh(x[0]) (+ hi/lo bf16); reset grid barrier
// ---------------------------------------------------------------------------
__global__ void __launch_bounds__(256) init_kernel()
{
    int i = blockIdx.x * blockDim.x + threadIdx.x;
    if (i < B_SZ * H_SZ) {
        float v = tanhf(g_x[i]);
        g_th[i] = v;
        split_bf16(v, g_th_hi[i], g_th_lo[i]);
    }
    if (i == 0) g_bar = 0u;
}

// ---------------------------------------------------------------------------
// Persistent recurrence scan; now also emits bf16 hi/lo of th directly.
// ---------------------------------------------------------------------------
extern __shared__ float smem_dyn[];

__global__ void __launch_bounds__(256) rnn_scan_kernel(const float* __restrict__ W_hh)
{
    float* sh_th = smem_dyn;
    float* psum  = smem_dyn + 16 * 1024;

    const int tid = threadIdx.x;
    const int n   = tid & 15;
    const int kc  = tid >> 4;
    const int n0  = blockIdx.x * 16;

    unsigned long long wq[32];
    {
        const ulonglong2* wp =
            (const ulonglong2*)(W_hh + (size_t)(n0 + n) * H_SZ + kc * 64);
#pragma unroll
        for (int t = 0; t < 16; ++t) {
            ulonglong2 u = wp[t];
            wq[2 * t]     = u.x;
            wq[2 * t + 1] = u.y;
        }
    }

    const int rb = tid >> 4;
    const int rn = tid & 15;
    unsigned* barp = &g_bar;

    for (int s = 1; s < S_LEN; ++s) {
        __syncthreads();
        if (tid == 0) {
            __threadfence();
            atomicAdd(barp, 1u);
            const unsigned target = 64u * (unsigned)s;
            unsigned v;
            do {
                asm volatile("ld.acquire.gpu.u32 %0, [%1];" : "=r"(v) : "l"(barp));
            } while (v < target);
        }
        __syncthreads();

        const float xv = g_x[(size_t)s * B_SZ * H_SZ + rb * H_SZ + n0 + rn];

        {
            const float4* src = (const float4*)(g_th + (size_t)(s - 1) * B_SZ * H_SZ);
            float4* dst = (float4*)sh_th;
#pragma unroll
            for (int t = 0; t < 16; ++t)
                dst[tid + 256 * t] = src[tid + 256 * t];
        }
        __syncthreads();

#pragma unroll 1
        for (int b = 0; b < 16; ++b) {
            const ulonglong2* tp = (const ulonglong2*)(sh_th + b * H_SZ + kc * 64);
            unsigned long long s0 = 0ull, s1 = 0ull;
#pragma unroll
            for (int t = 0; t < 16; ++t) {
                ulonglong2 u = tp[t];
                asm("fma.rn.f32x2 %0, %1, %2, %0;" : "+l"(s0) : "l"(wq[2 * t]),     "l"(u.x));
                asm("fma.rn.f32x2 %0, %1, %2, %0;" : "+l"(s1) : "l"(wq[2 * t + 1]), "l"(u.y));
            }
            float p0, p1, p2, p3;
            asm("mov.b64 {%0, %1}, %2;" : "=f"(p0), "=f"(p1) : "l"(s0));
            asm("mov.b64 {%0, %1}, %2;" : "=f"(p2), "=f"(p3) : "l"(s1));
            psum[kc * 256 + b * 16 + n] = (p0 + p1) + (p2 + p3);
        }
        __syncthreads();

        float acc = xv;
#pragma unroll
        for (int k2 = 0; k2 < 16; ++k2)
            acc += psum[k2 * 256 + rb * 16 + rn];
        const size_t oi = (size_t)s * B_SZ * H_SZ + rb * H_SZ + n0 + rn;
        const float v = tanhf(acc);
        g_th[oi] = v;
        split_bf16(v, g_th_hi[oi], g_th_lo[oi]);
    }
}

// ---------------------------------------------------------------------------
// W_out hi/lo bf16 split
// ---------------------------------------------------------------------------
__global__ void __launch_bounds__(256) convert_wo_kernel(const float* __restrict__ W_out)
{
    size_t total = (size_t)V_SZ * H_SZ;
    size_t stride = (size_t)gridDim.x * blockDim.x;
    for (size_t i = (size_t)blockIdx.x * blockDim.x + threadIdx.x; i < total; i += stride) {
        split_bf16(W_out[i], g_wo_hi[i], g_wo_lo[i]);
    }
}

// ---------------------------------------------------------------------------
// HMMA (mma.sync) bf16-split output GEMM:
//   C[4096, 32000] = th[4096,1024] @ W_out[32000,1024]^T + b_out
// BM=128, BN=128, BK=64. 512 threads = 16 warps = 4(M) x 4(N); warp tile 32x32.
// 3 terms per k-slice: Ah*Bh + Ah*Bl + Al*Bh (fp32 accum).
// cp.async double-buffered, SW128-swizzled smem, NON-trans ldmatrix.
// ---------------------------------------------------------------------------
#define KCHUNK   64
#define NKC      (H_SZ / KCHUNK)     // 16
#define TILE_SZ  (128 * 128)         // bytes per bf16 tile (128 rows x 64 bf16)
#define STAGE_SZ (4 * TILE_SZ)       // Ah Al Bh Bl = 64 KB
#define MMA_SMEM (1024 + 2 * STAGE_SZ)
#define MMA_NT   512

extern __shared__ char smem_raw[];

__device__ __forceinline__ void fill_stage(
    uint32_t sbase, int stage, int kc, int m0, int n0, int tid)
{
    const uint32_t st = sbase + (uint32_t)stage * STAGE_SZ;
#pragma unroll
    for (int i = 0; i < 2; ++i) {
        int ch = tid + MMA_NT * i;            // 0..1023
        int r = ch >> 3, c = ch & 7;
        uint32_t so = SMEM_SWIZZLE_128B((uint32_t)(r * 128 + c * 16));
        size_t ga = (size_t)(m0 + r) * H_SZ + kc * KCHUNK + c * 8;
        cp16(st + so,               g_th_hi + ga);
        cp16(st + TILE_SZ + so,     g_th_lo + ga);
        size_t gb = (size_t)(n0 + r) * H_SZ + kc * KCHUNK + c * 8;
        cp16(st + 2 * TILE_SZ + so, g_wo_hi + gb);
        cp16(st + 3 * TILE_SZ + so, g_wo_lo + gb);
    }
}

__global__ void __launch_bounds__(MMA_NT, 1) mma_out_kernel(
    const float* __restrict__ b_out, float* __restrict__ C)
{
    const uint32_t sbase = (smem_to_u32(smem_raw) + 1023u) & ~1023u;

    const int tid    = threadIdx.x;
    const int wid    = tid >> 5;
    const int lane   = tid & 31;
    const int warp_m = wid & 3;       // 0..3 -> 32 rows each
    const int warp_n = wid >> 2;      // 0..3 -> 32 cols each

    const int m0 = blockIdx.y * 128;
    const int n0 = blockIdx.x * 128;

    // ldmatrix per-lane address components (all NON-trans)
    // A: r0 = m0-7/k0-7, r1 = m8-15/k0-7, r2 = m0-7/k8-15, r3 = m8-15/k8-15
    const int a_row = warp_m * 32 + ((lane >> 3) & 1) * 8 + (lane & 7);
    const int a_kb  = ((lane >> 4) & 1) * 16;
    // B: r0 = n0-7/k0-7, r1 = n0-7/k8-15, r2/r3 = n8-15 pair
    const int b_row = warp_n * 32 + ((lane >> 4) & 1) * 8 + (lane & 7);
    const int b_kb  = ((lane >> 3) & 1) * 16;

    float acc[2][4][4];
#pragma unroll
    for (int i = 0; i < 2; i++)
#pragma unroll
        for (int j = 0; j < 4; j++)
#pragma unroll
            for (int k = 0; k < 4; k++) acc[i][j][k] = 0.f;

    fill_stage(sbase, 0, 0, m0, n0, tid);
    cp_commit();

    for (int kc = 0; kc < NKC; ++kc) {
        const int buf = kc & 1;
        if (kc + 1 < NKC) {
            fill_stage(sbase, buf ^ 1, kc + 1, m0, n0, tid);
            cp_commit();
            cp_wait<1>();
        } else {
            cp_wait<0>();
        }
        __syncthreads();

        const uint32_t st = sbase + (uint32_t)buf * STAGE_SZ;

#pragma unroll
        for (int ks = 0; ks < 4; ++ks) {
            uint32_t ah[2][4], al[2][4];
#pragma unroll
            for (int mt = 0; mt < 2; ++mt) {
                uint32_t off = (uint32_t)((a_row + mt * 16) * 128 + ks * 32 + a_kb);
                uint32_t so  = SMEM_SWIZZLE_128B(off);
                ldsm_x4(ah[mt], st + so);
                ldsm_x4(al[mt], st + TILE_SZ + so);
            }
            uint32_t bh[2][4], bl[2][4];   // each x4 = two n8 frags
#pragma unroll
            for (int np = 0; np < 2; ++np) {
                uint32_t off = (uint32_t)((b_row + np * 16) * 128 + ks * 32 + b_kb);
                uint32_t so  = SMEM_SWIZZLE_128B(off);
                ldsm_x4(bh[np], st + 2 * TILE_SZ + so);
                ldsm_x4(bl[np], st + 3 * TILE_SZ + so);
            }
#pragma unroll
            for (int mt = 0; mt < 2; ++mt) {
#pragma unroll
                for (int nt = 0; nt < 4; ++nt) {
                    const uint32_t* bhf = &bh[nt >> 1][(nt & 1) * 2];
                    const uint32_t* blf = &bl[nt >> 1][(nt & 1) * 2];
                    mma16816(acc[mt][nt], ah[mt], bhf);
                    mma16816(acc[mt][nt], ah[mt], blf);
                    mma16816(acc[mt][nt], al[mt], bhf);
                }
            }
        }
        __syncthreads();
    }

    // epilogue
    const int group = lane >> 2;
    const int tig   = lane & 3;
#pragma unroll
    for (int nt = 0; nt < 4; ++nt) {
        const int col = n0 + warp_n * 32 + nt * 8 + tig * 2;
        const float2 bv = *(const float2*)(b_out + col);
#pragma unroll
        for (int mt = 0; mt < 2; ++mt) {
            const int row0 = m0 + warp_m * 32 + mt * 16 + group;
            float2 v0, v1;
            v0.x = acc[mt][nt][0] + bv.x;
            v0.y = acc[mt][nt][1] + bv.y;
            v1.x = acc[mt][nt][2] + bv.x;
            v1.y = acc[mt][nt][3] + bv.y;
            *(float2*)(C + (size_t)row0 * V_SZ + col)       = v0;
            *(float2*)(C + (size_t)(row0 + 8) * V_SZ + col) = v1;
        }
    }
}

// ---------------------------------------------------------------------------
// kernel_launch
// ---------------------------------------------------------------------------
extern "C" void kernel_launch(void* const* d_in, const int* in_sizes, int n_in,
                              void* d_out, int out_size)
{
    (void)in_sizes; (void)n_in; (void)out_size;
    const int*   tokens = (const int*)  d_in[0];
    const float* emb    = (const float*)d_in[1];
    const float* W_in   = (const float*)d_in[2];
    const float* W_hh   = (const float*)d_in[3];
    const float* W_out  = (const float*)d_in[4];
    const float* b_out  = (const float*)d_in[5];
    float* out = (float*)d_out;

    float* gx = nullptr;
    cudaGetSymbolAddress((void**)&gx, g_x);

    // 0) W_out hi/lo bf16 split
    convert_wo_kernel<<<2048, 256>>>(W_out);

    // 1) x = gather(emb) @ W_in^T
    sgemm128_nt<true><<<dim3(H_SZ / 128, M_SZ / 128), 256>>>(
        emb, W_in, nullptr, tokens, gx, H_SZ, E_SZ);

    // 2) th[0] = tanh(x[0]) + bf16 split; reset barrier
    init_kernel<<<(B_SZ * H_SZ + 255) / 256, 256>>>();

    // 3) persistent recurrence (emits fp32 + bf16 hi/lo)
    const int scan_smem = (16 * 1024 + 16 * 16 * 16) * (int)sizeof(float);
    cudaFuncSetAttribute(rnn_scan_kernel,
                         cudaFuncAttributeMaxDynamicSharedMemorySize, scan_smem);
    rnn_scan_kernel<<<H_SZ / 16, 256, scan_smem>>>(W_hh);

    // 4) logits = th @ W_out^T + b_out via HMMA (3-term bf16 split), 16 warps
    cudaFuncSetAttribute(mma_out_kernel,
                         cudaFuncAttributeMaxDynamicSharedMemorySize, MMA_SMEM);
    mma_out_kernel<<<dim3(V_SZ / 128, M_SZ / 128), MMA_NT, MMA_SMEM>>>(b_out, out);
}

// round 13
// speedup vs baseline: 1.0480x; 1.0480x over previous
#include <cuda_runtime.h>
#include <cuda_bf16.h>
#include <math.h>
#include <stdint.h>

#define S_LEN 256
#define B_SZ  16
#define V_SZ  32000
#define E_SZ  512
#define H_SZ  1024
#define M_SZ  (S_LEN * B_SZ)   // 4096

// ---------------------------------------------------------------------------
// Device scratch (static — no runtime allocation allowed)
// ---------------------------------------------------------------------------
__device__ float    g_x [M_SZ * H_SZ];
__device__ float    g_th[M_SZ * H_SZ];
__device__ unsigned g_bar;
__device__ __align__(16) __nv_bfloat16 g_th_hi[M_SZ * H_SZ];
__device__ __align__(16) __nv_bfloat16 g_th_lo[M_SZ * H_SZ];
__device__ __align__(16) __nv_bfloat16 g_wo_hi[(size_t)V_SZ * H_SZ];
__device__ __align__(16) __nv_bfloat16 g_wo_lo[(size_t)V_SZ * H_SZ];

#define SMEM_SWIZZLE_128B(o) ((o) ^ (((o) >> 3) & 0x70))

__device__ __forceinline__ uint32_t smem_to_u32(const void* p) {
    uint32_t a;
    asm("{ .reg .u64 t; cvta.to.shared.u64 t, %1; cvt.u32.u64 %0, t; }"
        : "=r"(a) : "l"(p));
    return a;
}

__device__ __forceinline__ void cp16(uint32_t saddr, const void* g) {
    unsigned long long ga = (unsigned long long)__cvta_generic_to_global(g);
    asm volatile("cp.async.cg.shared.global [%0], [%1], 16;"
                 :: "r"(saddr), "l"(ga) : "memory");
}
__device__ __forceinline__ void cp_commit() {
    asm volatile("cp.async.commit_group;" ::: "memory");
}
template<int N>
__device__ __forceinline__ void cp_wait() {
    asm volatile("cp.async.wait_group %0;" :: "n"(N) : "memory");
}

__device__ __forceinline__ void ldsm_x4(uint32_t* r, uint32_t addr) {
    asm volatile("ldmatrix.sync.aligned.m8n8.x4.shared.b16 {%0,%1,%2,%3}, [%4];"
                 : "=r"(r[0]), "=r"(r[1]), "=r"(r[2]), "=r"(r[3]) : "r"(addr));
}
__device__ __forceinline__ void mma16816(float* d, const uint32_t* a, const uint32_t* b) {
    asm volatile(
        "mma.sync.aligned.m16n8k16.row.col.f32.bf16.bf16.f32 "
        "{%0,%1,%2,%3}, {%4,%5,%6,%7}, {%8,%9}, {%0,%1,%2,%3};"
        : "+f"(d[0]), "+f"(d[1]), "+f"(d[2]), "+f"(d[3])
        : "r"(a[0]), "r"(a[1]), "r"(a[2]), "r"(a[3]), "r"(b[0]), "r"(b[1]));
}

// ---------------------------------------------------------------------------
// Scalar NT SGEMM (f32x2) — input projection only (M=4096,N=1024,K=512)
// ---------------------------------------------------------------------------
template<bool GATHER>
__global__ void __launch_bounds__(256) sgemm128_nt(
    const float* __restrict__ A,
    const float* __restrict__ B,
    const float* __restrict__ bias,
    const int*   __restrict__ tokens,
    float* __restrict__ C,
    int N, int K)
{
    __shared__ float As[2][8][128];
    __shared__ float Bs[2][8][128];

    const int tid = threadIdx.x;
    const int bm  = blockIdx.y;
    const int bn  = blockIdx.x;

    const int lrow = tid >> 1;
    const int lk   = (tid & 1) << 2;

    const float* Arow;
    if (GATHER) {
        const int tok = tokens[bm * 128 + lrow];
        Arow = A + (size_t)tok * K;
    } else {
        Arow = A + (size_t)(bm * 128 + lrow) * K;
    }
    const float* Brow = B + (size_t)(bn * 128 + lrow) * K;

    const int tx = tid & 15;
    const int ty = tid >> 4;

    unsigned long long acc2[8][4];
#pragma unroll
    for (int i = 0; i < 8; i++)
#pragma unroll
        for (int jp = 0; jp < 4; jp++) acc2[i][jp] = 0ull;

    {
        float4 a4 = *(const float4*)(Arow + lk);
        float4 b4 = *(const float4*)(Brow + lk);
        As[0][lk + 0][lrow] = a4.x; As[0][lk + 1][lrow] = a4.y;
        As[0][lk + 2][lrow] = a4.z; As[0][lk + 3][lrow] = a4.w;
        Bs[0][lk + 0][lrow] = b4.x; Bs[0][lk + 1][lrow] = b4.y;
        Bs[0][lk + 2][lrow] = b4.z; Bs[0][lk + 3][lrow] = b4.w;
    }
    __syncthreads();

    const int nt = K >> 3;
    for (int t = 0; t < nt; ++t) {
        const int cur = t & 1;
        float4 na, nb;
        if (t + 1 < nt) {
            na = *(const float4*)(Arow + (t + 1) * 8 + lk);
            nb = *(const float4*)(Brow + (t + 1) * 8 + lk);
        }
#pragma unroll
        for (int k = 0; k < 8; k++) {
            float af[8];
            *(float4*)(af)     = *(const float4*)&As[cur][k][ty * 8];
            *(float4*)(af + 4) = *(const float4*)&As[cur][k][ty * 8 + 4];
            ulonglong2 b01 = *(const ulonglong2*)&Bs[cur][k][tx * 8];
            ulonglong2 b23 = *(const ulonglong2*)&Bs[cur][k][tx * 8 + 4];
#pragma unroll
            for (int i = 0; i < 8; i++) {
                unsigned long long ai;
                asm("mov.b64 %0, {%1, %1};" : "=l"(ai) : "f"(af[i]));
                asm("fma.rn.f32x2 %0, %1, %2, %0;" : "+l"(acc2[i][0]) : "l"(ai), "l"(b01.x));
                asm("fma.rn.f32x2 %0, %1, %2, %0;" : "+l"(acc2[i][1]) : "l"(ai), "l"(b01.y));
                asm("fma.rn.f32x2 %0, %1, %2, %0;" : "+l"(acc2[i][2]) : "l"(ai), "l"(b23.x));
                asm("fma.rn.f32x2 %0, %1, %2, %0;" : "+l"(acc2[i][3]) : "l"(ai), "l"(b23.y));
            }
        }
        if (t + 1 < nt) {
            const int nxt = cur ^ 1;
            As[nxt][lk + 0][lrow] = na.x; As[nxt][lk + 1][lrow] = na.y;
            As[nxt][lk + 2][lrow] = na.z; As[nxt][lk + 3][lrow] = na.w;
            Bs[nxt][lk + 0][lrow] = nb.x; Bs[nxt][lk + 1][lrow] = nb.y;
            Bs[nxt][lk + 2][lrow] = nb.z; Bs[nxt][lk + 3][lrow] = nb.w;
            __syncthreads();
        }
    }

    const int gm0 = bm * 128 + ty * 8;
    const int gn0 = bn * 128 + tx * 8;
    float bb[8];
    if (bias) {
        *(float4*)(bb)     = *(const float4*)(bias + gn0);
        *(float4*)(bb + 4) = *(const float4*)(bias + gn0 + 4);
    } else {
#pragma unroll
        for (int j = 0; j < 8; j++) bb[j] = 0.f;
    }
#pragma unroll
    for (int i = 0; i < 8; i++) {
        float cv[8];
#pragma unroll
        for (int jp = 0; jp < 4; jp++) {
            float lo, hi;
            asm("mov.b64 {%0, %1}, %2;" : "=f"(lo), "=f"(hi) : "l"(acc2[i][jp]));
            cv[2 * jp]     = lo + bb[2 * jp];
            cv[2 * jp + 1] = hi + bb[2 * jp + 1];
        }
        float* crow = C + (size_t)(gm0 + i) * N + gn0;
        *(float4*)(crow)     = *(float4*)(cv);
        *(float4*)(crow + 4) = *(float4*)(cv + 4);
    }
}

// ---------------------------------------------------------------------------
// hi/lo split helper
// ---------------------------------------------------------------------------
__device__ __forceinline__ void split_bf16(float x, __nv_bfloat16& hi, __nv_bfloat16& lo)
{
    hi = __float2bfloat16(x);
    lo = __float2bfloat16(x - __bfloat162float(hi));
}

// ---------------------------------------------------------------------------
// init: th[0] = tanh(x[0]) (+ hi/lo bf16); reset grid barrier
// ---------------------------------------------------------------------------
__global__ void __launch_bounds__(256) init_kernel()
{
    int i = blockIdx.x * blockDim.x + threadIdx.x;
    if (i < B_SZ * H_SZ) {
        float v = tanhf(g_x[i]);
        g_th[i] = v;
        split_bf16(v, g_th_hi[i], g_th_lo[i]);
    }
    if (i == 0) g_bar = 0u;
}

// ---------------------------------------------------------------------------
// Persistent recurrence scan; emits fp32 th and bf16 hi/lo.
// ---------------------------------------------------------------------------
extern __shared__ float smem_dyn[];

__global__ void __launch_bounds__(256) rnn_scan_kernel(const float* __restrict__ W_hh)
{
    float* sh_th = smem_dyn;
    float* psum  = smem_dyn + 16 * 1024;

    const int tid = threadIdx.x;
    const int n   = tid & 15;
    const int kc  = tid >> 4;
    const int n0  = blockIdx.x * 16;

    unsigned long long wq[32];
    {
        const ulonglong2* wp =
            (const ulonglong2*)(W_hh + (size_t)(n0 + n) * H_SZ + kc * 64);
#pragma unroll
        for (int t = 0; t < 16; ++t) {
            ulonglong2 u = wp[t];
            wq[2 * t]     = u.x;
            wq[2 * t + 1] = u.y;
        }
    }

    const int rb = tid >> 4;
    const int rn = tid & 15;
    unsigned* barp = &g_bar;

    for (int s = 1; s < S_LEN; ++s) {
        __syncthreads();
        if (tid == 0) {
            __threadfence();
            atomicAdd(barp, 1u);
            const unsigned target = 64u * (unsigned)s;
            unsigned v;
            do {
                asm volatile("ld.acquire.gpu.u32 %0, [%1];" : "=r"(v) : "l"(barp));
            } while (v < target);
        }
        __syncthreads();

        const float xv = g_x[(size_t)s * B_SZ * H_SZ + rb * H_SZ + n0 + rn];

        {
            const float4* src = (const float4*)(g_th + (size_t)(s - 1) * B_SZ * H_SZ);
            float4* dst = (float4*)sh_th;
#pragma unroll
            for (int t = 0; t < 16; ++t)
                dst[tid + 256 * t] = src[tid + 256 * t];
        }
        __syncthreads();

#pragma unroll 1
        for (int b = 0; b < 16; ++b) {
            const ulonglong2* tp = (const ulonglong2*)(sh_th + b * H_SZ + kc * 64);
            unsigned long long s0 = 0ull, s1 = 0ull;
#pragma unroll
            for (int t = 0; t < 16; ++t) {
                ulonglong2 u = tp[t];
                asm("fma.rn.f32x2 %0, %1, %2, %0;" : "+l"(s0) : "l"(wq[2 * t]),     "l"(u.x));
                asm("fma.rn.f32x2 %0, %1, %2, %0;" : "+l"(s1) : "l"(wq[2 * t + 1]), "l"(u.y));
            }
            float p0, p1, p2, p3;
            asm("mov.b64 {%0, %1}, %2;" : "=f"(p0), "=f"(p1) : "l"(s0));
            asm("mov.b64 {%0, %1}, %2;" : "=f"(p2), "=f"(p3) : "l"(s1));
            psum[kc * 256 + b * 16 + n] = (p0 + p1) + (p2 + p3);
        }
        __syncthreads();

        float acc = xv;
#pragma unroll
        for (int k2 = 0; k2 < 16; ++k2)
            acc += psum[k2 * 256 + rb * 16 + rn];
        const size_t oi = (size_t)s * B_SZ * H_SZ + rb * H_SZ + n0 + rn;
        const float v = tanhf(acc);
        g_th[oi] = v;
        split_bf16(v, g_th_hi[oi], g_th_lo[oi]);
    }
}

// ---------------------------------------------------------------------------
// W_out hi/lo bf16 split
// ---------------------------------------------------------------------------
__global__ void __launch_bounds__(256) convert_wo_kernel(const float* __restrict__ W_out)
{
    size_t total = (size_t)V_SZ * H_SZ;
    size_t stride = (size_t)gridDim.x * blockDim.x;
    for (size_t i = (size_t)blockIdx.x * blockDim.x + threadIdx.x; i < total; i += stride) {
        split_bf16(W_out[i], g_wo_hi[i], g_wo_lo[i]);
    }
}

// ---------------------------------------------------------------------------
// HMMA (mma.sync) bf16-split output GEMM:
//   C[4096, 32000] = th[4096,1024] @ W_out[32000,1024]^T + b_out
// BM=128, BN=256, BK=64. 8 warps = 2(M) x 4(N); warp tile 64x64.
// 3 terms per k-slice: Ah*Bh + Ah*Bl + Al*Bh (fp32 accum).
// cp.async double-buffered, SW128-swizzled smem, NON-trans ldmatrix.
// ldsm:MMA ratio = 16:96 per ks-slice (vs 12:48 in the 64x32 variant).
// ---------------------------------------------------------------------------
#define KCHUNK    64
#define NKC       (H_SZ / KCHUNK)    // 16
#define BN_TILE   256
#define A_TSZ     (128 * 128)        // 16 KB per A bf16 tile
#define B_TSZ     (BN_TILE * 128)    // 32 KB per B bf16 tile
#define STAGE_SZ  (2 * A_TSZ + 2 * B_TSZ)   // 96 KB
#define MMA_SMEM  (1024 + 2 * STAGE_SZ)     // ~193 KB
#define MMA_NT    256

extern __shared__ char smem_raw[];

__device__ __forceinline__ void fill_stage(
    uint32_t sbase, int stage, int kc, int m0, int n0, int tid)
{
    const uint32_t st = sbase + (uint32_t)stage * STAGE_SZ;
    // A: 128 rows x 64 bf16 = 1024 16B-chunks (4/thread), hi + lo
#pragma unroll
    for (int i = 0; i < 4; ++i) {
        int ch = tid + MMA_NT * i;
        int r = ch >> 3, c = ch & 7;
        uint32_t so = SMEM_SWIZZLE_128B((uint32_t)(r * 128 + c * 16));
        size_t ga = (size_t)(m0 + r) * H_SZ + kc * KCHUNK + c * 8;
        cp16(st + so,         g_th_hi + ga);
        cp16(st + A_TSZ + so, g_th_lo + ga);
    }
    // B: 256 rows x 64 bf16 = 2048 16B-chunks (8/thread), hi + lo
#pragma unroll
    for (int i = 0; i < 8; ++i) {
        int ch = tid + MMA_NT * i;
        int r = ch >> 3, c = ch & 7;
        uint32_t so = SMEM_SWIZZLE_128B((uint32_t)(r * 128 + c * 16));
        size_t gb = (size_t)(n0 + r) * H_SZ + kc * KCHUNK + c * 8;
        cp16(st + 2 * A_TSZ + so,         g_wo_hi + gb);
        cp16(st + 2 * A_TSZ + B_TSZ + so, g_wo_lo + gb);
    }
}

__global__ void __launch_bounds__(MMA_NT, 1) mma_out_kernel(
    const float* __restrict__ b_out, float* __restrict__ C)
{
    const uint32_t sbase = (smem_to_u32(smem_raw) + 1023u) & ~1023u;

    const int tid    = threadIdx.x;
    const int wid    = tid >> 5;
    const int lane   = tid & 31;
    const int warp_m = wid & 1;       // 0..1 -> 64 rows
    const int warp_n = wid >> 1;      // 0..3 -> 64 cols

    const int m0 = blockIdx.y * 128;
    const int n0 = blockIdx.x * BN_TILE;

    // ldmatrix lane address components (NON-trans)
    const int a_row = warp_m * 64 + ((lane >> 3) & 1) * 8 + (lane & 7);
    const int a_kb  = ((lane >> 4) & 1) * 16;
    const int b_lrow = ((lane >> 4) & 1) * 8 + (lane & 7);   // + warp_n*64 + np*16
    const int b_kb   = ((lane >> 3) & 1) * 16;

    float acc[4][8][4];
#pragma unroll
    for (int i = 0; i < 4; i++)
#pragma unroll
        for (int j = 0; j < 8; j++)
#pragma unroll
            for (int k = 0; k < 4; k++) acc[i][j][k] = 0.f;

    fill_stage(sbase, 0, 0, m0, n0, tid);
    cp_commit();

    for (int kc = 0; kc < NKC; ++kc) {
        const int buf = kc & 1;
        if (kc + 1 < NKC) {
            fill_stage(sbase, buf ^ 1, kc + 1, m0, n0, tid);
            cp_commit();
            cp_wait<1>();
        } else {
            cp_wait<0>();
        }
        __syncthreads();

        const uint32_t st = sbase + (uint32_t)buf * STAGE_SZ;
        const uint32_t stA  = st;
        const uint32_t stAl = st + A_TSZ;
        const uint32_t stB  = st + 2 * A_TSZ;
        const uint32_t stBl = st + 2 * A_TSZ + B_TSZ;

#pragma unroll
        for (int ks = 0; ks < 4; ++ks) {
            uint32_t ah[4][4], al[4][4];
#pragma unroll
            for (int mt = 0; mt < 4; ++mt) {
                uint32_t off = (uint32_t)((a_row + mt * 16) * 128 + ks * 32 + a_kb);
                uint32_t so  = SMEM_SWIZZLE_128B(off);
                ldsm_x4(ah[mt], stA  + so);
                ldsm_x4(al[mt], stAl + so);
            }
            uint32_t bh[4][4], bl[4][4];   // np: 16-col groups; each x4 = 2 n8 frags
#pragma unroll
            for (int np = 0; np < 4; ++np) {
                uint32_t row = (uint32_t)(warp_n * 64 + np * 16 + b_lrow);
                uint32_t off = row * 128 + ks * 32 + b_kb;
                uint32_t so  = SMEM_SWIZZLE_128B(off);
                ldsm_x4(bh[np], stB  + so);
                ldsm_x4(bl[np], stBl + so);
            }
#pragma unroll
            for (int mt = 0; mt < 4; ++mt) {
#pragma unroll
                for (int nt = 0; nt < 8; ++nt) {
                    const uint32_t* bhf = &bh[nt >> 1][(nt & 1) * 2];
                    const uint32_t* blf = &bl[nt >> 1][(nt & 1) * 2];
                    mma16816(acc[mt][nt], ah[mt], bhf);
                    mma16816(acc[mt][nt], ah[mt], blf);
                    mma16816(acc[mt][nt], al[mt], bhf);
                }
            }
        }
        __syncthreads();
    }

    // epilogue
    const int group = lane >> 2;
    const int tig   = lane & 3;
#pragma unroll
    for (int nt = 0; nt < 8; ++nt) {
        const int col = n0 + warp_n * 64 + nt * 8 + tig * 2;
        const float2 bv = *(const float2*)(b_out + col);
#pragma unroll
        for (int mt = 0; mt < 4; ++mt) {
            const int row0 = m0 + warp_m * 64 + mt * 16 + group;
            float2 v0, v1;
            v0.x = acc[mt][nt][0] + bv.x;
            v0.y = acc[mt][nt][1] + bv.y;
            v1.x = acc[mt][nt][2] + bv.x;
            v1.y = acc[mt][nt][3] + bv.y;
            *(float2*)(C + (size_t)row0 * V_SZ + col)       = v0;
            *(float2*)(C + (size_t)(row0 + 8) * V_SZ + col) = v1;
        }
    }
}

// ---------------------------------------------------------------------------
// kernel_launch
// ---------------------------------------------------------------------------
extern "C" void kernel_launch(void* const* d_in, const int* in_sizes, int n_in,
                              void* d_out, int out_size)
{
    (void)in_sizes; (void)n_in; (void)out_size;
    const int*   tokens = (const int*)  d_in[0];
    const float* emb    = (const float*)d_in[1];
    const float* W_in   = (const float*)d_in[2];
    const float* W_hh   = (const float*)d_in[3];
    const float* W_out  = (const float*)d_in[4];
    const float* b_out  = (const float*)d_in[5];
    float* out = (float*)d_out;

    float* gx = nullptr;
    cudaGetSymbolAddress((void**)&gx, g_x);

    // 0) W_out hi/lo bf16 split
    convert_wo_kernel<<<2048, 256>>>(W_out);

    // 1) x = gather(emb) @ W_in^T
    sgemm128_nt<true><<<dim3(H_SZ / 128, M_SZ / 128), 256>>>(
        emb, W_in, nullptr, tokens, gx, H_SZ, E_SZ);

    // 2) th[0] = tanh(x[0]) + bf16 split; reset barrier
    init_kernel<<<(B_SZ * H_SZ + 255) / 256, 256>>>();

    // 3) persistent recurrence (emits fp32 + bf16 hi/lo)
    const int scan_smem = (16 * 1024 + 16 * 16 * 16) * (int)sizeof(float);
    cudaFuncSetAttribute(rnn_scan_kernel,
                         cudaFuncAttributeMaxDynamicSharedMemorySize, scan_smem);
    rnn_scan_kernel<<<H_SZ / 16, 256, scan_smem>>>(W_hh);

    // 4) logits = th @ W_out^T + b_out via HMMA (3-term bf16 split),
    //    BM=128 x BN=256, 8 warps, 64x64 warp tiles
    cudaFuncSetAttribute(mma_out_kernel,
                         cudaFuncAttributeMaxDynamicSharedMemorySize, MMA_SMEM);
    mma_out_kernel<<<dim3(V_SZ / BN_TILE, M_SZ / 128), MMA_NT, MMA_SMEM>>>(b_out, out);
}

// round 14
// speedup vs baseline: 1.2826x; 1.2239x over previous
#include <cuda_runtime.h>
#include <cuda_fp16.h>
#include <math.h>
#include <stdint.h>

#define S_LEN 256
#define B_SZ  16
#define V_SZ  32000
#define E_SZ  512
#define H_SZ  1024
#define M_SZ  (S_LEN * B_SZ)   // 4096

// ---------------------------------------------------------------------------
// Device scratch (static — no runtime allocation allowed)
// ---------------------------------------------------------------------------
__device__ float    g_x [M_SZ * H_SZ];
__device__ float    g_th[M_SZ * H_SZ];
__device__ unsigned g_bar;
__device__ __align__(16) __half g_th_hi[M_SZ * H_SZ];
__device__ __align__(16) __half g_th_lo[M_SZ * H_SZ];
__device__ __align__(16) __half g_wo_h [(size_t)V_SZ * H_SZ];

#define SMEM_SWIZZLE_128B(o) ((o) ^ (((o) >> 3) & 0x70))

__device__ __forceinline__ uint32_t smem_to_u32(const void* p) {
    uint32_t a;
    asm("{ .reg .u64 t; cvta.to.shared.u64 t, %1; cvt.u32.u64 %0, t; }"
        : "=r"(a) : "l"(p));
    return a;
}

__device__ __forceinline__ void cp16(uint32_t saddr, const void* g) {
    unsigned long long ga = (unsigned long long)__cvta_generic_to_global(g);
    asm volatile("cp.async.cg.shared.global [%0], [%1], 16;"
                 :: "r"(saddr), "l"(ga) : "memory");
}
__device__ __forceinline__ void cp_commit() {
    asm volatile("cp.async.commit_group;" ::: "memory");
}
template<int N>
__device__ __forceinline__ void cp_wait() {
    asm volatile("cp.async.wait_group %0;" :: "n"(N) : "memory");
}

__device__ __forceinline__ void ldsm_x4(uint32_t* r, uint32_t addr) {
    asm volatile("ldmatrix.sync.aligned.m8n8.x4.shared.b16 {%0,%1,%2,%3}, [%4];"
                 : "=r"(r[0]), "=r"(r[1]), "=r"(r[2]), "=r"(r[3]) : "r"(addr));
}
__device__ __forceinline__ void mma16816h(float* d, const uint32_t* a, const uint32_t* b) {
    asm volatile(
        "mma.sync.aligned.m16n8k16.row.col.f32.f16.f16.f32 "
        "{%0,%1,%2,%3}, {%4,%5,%6,%7}, {%8,%9}, {%0,%1,%2,%3};"
        : "+f"(d[0]), "+f"(d[1]), "+f"(d[2]), "+f"(d[3])
        : "r"(a[0]), "r"(a[1]), "r"(a[2]), "r"(a[3]), "r"(b[0]), "r"(b[1]));
}

// ---------------------------------------------------------------------------
// Scalar NT SGEMM (f32x2) — input projection only (M=4096,N=1024,K=512)
// ---------------------------------------------------------------------------
template<bool GATHER>
__global__ void __launch_bounds__(256) sgemm128_nt(
    const float* __restrict__ A,
    const float* __restrict__ B,
    const float* __restrict__ bias,
    const int*   __restrict__ tokens,
    float* __restrict__ C,
    int N, int K)
{
    __shared__ float As[2][8][128];
    __shared__ float Bs[2][8][128];

    const int tid = threadIdx.x;
    const int bm  = blockIdx.y;
    const int bn  = blockIdx.x;

    const int lrow = tid >> 1;
    const int lk   = (tid & 1) << 2;

    const float* Arow;
    if (GATHER) {
        const int tok = tokens[bm * 128 + lrow];
        Arow = A + (size_t)tok * K;
    } else {
        Arow = A + (size_t)(bm * 128 + lrow) * K;
    }
    const float* Brow = B + (size_t)(bn * 128 + lrow) * K;

    const int tx = tid & 15;
    const int ty = tid >> 4;

    unsigned long long acc2[8][4];
#pragma unroll
    for (int i = 0; i < 8; i++)
#pragma unroll
        for (int jp = 0; jp < 4; jp++) acc2[i][jp] = 0ull;

    {
        float4 a4 = *(const float4*)(Arow + lk);
        float4 b4 = *(const float4*)(Brow + lk);
        As[0][lk + 0][lrow] = a4.x; As[0][lk + 1][lrow] = a4.y;
        As[0][lk + 2][lrow] = a4.z; As[0][lk + 3][lrow] = a4.w;
        Bs[0][lk + 0][lrow] = b4.x; Bs[0][lk + 1][lrow] = b4.y;
        Bs[0][lk + 2][lrow] = b4.z; Bs[0][lk + 3][lrow] = b4.w;
    }
    __syncthreads();

    const int nt = K >> 3;
    for (int t = 0; t < nt; ++t) {
        const int cur = t & 1;
        float4 na, nb;
        if (t + 1 < nt) {
            na = *(const float4*)(Arow + (t + 1) * 8 + lk);
            nb = *(const float4*)(Brow + (t + 1) * 8 + lk);
        }
#pragma unroll
        for (int k = 0; k < 8; k++) {
            float af[8];
            *(float4*)(af)     = *(const float4*)&As[cur][k][ty * 8];
            *(float4*)(af + 4) = *(const float4*)&As[cur][k][ty * 8 + 4];
            ulonglong2 b01 = *(const ulonglong2*)&Bs[cur][k][tx * 8];
            ulonglong2 b23 = *(const ulonglong2*)&Bs[cur][k][tx * 8 + 4];
#pragma unroll
            for (int i = 0; i < 8; i++) {
                unsigned long long ai;
                asm("mov.b64 %0, {%1, %1};" : "=l"(ai) : "f"(af[i]));
                asm("fma.rn.f32x2 %0, %1, %2, %0;" : "+l"(acc2[i][0]) : "l"(ai), "l"(b01.x));
                asm("fma.rn.f32x2 %0, %1, %2, %0;" : "+l"(acc2[i][1]) : "l"(ai), "l"(b01.y));
                asm("fma.rn.f32x2 %0, %1, %2, %0;" : "+l"(acc2[i][2]) : "l"(ai), "l"(b23.x));
                asm("fma.rn.f32x2 %0, %1, %2, %0;" : "+l"(acc2[i][3]) : "l"(ai), "l"(b23.y));
            }
        }
        if (t + 1 < nt) {
            const int nxt = cur ^ 1;
            As[nxt][lk + 0][lrow] = na.x; As[nxt][lk + 1][lrow] = na.y;
            As[nxt][lk + 2][lrow] = na.z; As[nxt][lk + 3][lrow] = na.w;
            Bs[nxt][lk + 0][lrow] = nb.x; Bs[nxt][lk + 1][lrow] = nb.y;
            Bs[nxt][lk + 2][lrow] = nb.z; Bs[nxt][lk + 3][lrow] = nb.w;
            __syncthreads();
        }
    }

    const int gm0 = bm * 128 + ty * 8;
    const int gn0 = bn * 128 + tx * 8;
    float bb[8];
    if (bias) {
        *(float4*)(bb)     = *(const float4*)(bias + gn0);
        *(float4*)(bb + 4) = *(const float4*)(bias + gn0 + 4);
    } else {
#pragma unroll
        for (int j = 0; j < 8; j++) bb[j] = 0.f;
    }
#pragma unroll
    for (int i = 0; i < 8; i++) {
        float cv[8];
#pragma unroll
        for (int jp = 0; jp < 4; jp++) {
            float lo, hi;
            asm("mov.b64 {%0, %1}, %2;" : "=f"(lo), "=f"(hi) : "l"(acc2[i][jp]));
            cv[2 * jp]     = lo + bb[2 * jp];
            cv[2 * jp + 1] = hi + bb[2 * jp + 1];
        }
        float* crow = C + (size_t)(gm0 + i) * N + gn0;
        *(float4*)(crow)     = *(float4*)(cv);
        *(float4*)(crow + 4) = *(float4*)(cv + 4);
    }
}

// ---------------------------------------------------------------------------
// fp16 hi/lo split helper: x = hi + lo with |lo| <= 2^-12 |x| (+2^-24 rounding)
// ---------------------------------------------------------------------------
__device__ __forceinline__ void split_fp16(float x, __half& hi, __half& lo)
{
    hi = __float2half_rn(x);
    lo = __float2half_rn(x - __half2float(hi));
}

// ---------------------------------------------------------------------------
// init: th[0] = tanh(x[0]) (+ fp16 hi/lo); reset grid barrier
// ---------------------------------------------------------------------------
__global__ void __launch_bounds__(256) init_kernel()
{
    int i = blockIdx.x * blockDim.x + threadIdx.x;
    if (i < B_SZ * H_SZ) {
        float v = tanhf(g_x[i]);
        g_th[i] = v;
        split_fp16(v, g_th_hi[i], g_th_lo[i]);
    }
    if (i == 0) g_bar = 0u;
}

// ---------------------------------------------------------------------------
// Persistent recurrence scan; emits fp32 th and fp16 hi/lo.
// ---------------------------------------------------------------------------
extern __shared__ float smem_dyn[];

__global__ void __launch_bounds__(256) rnn_scan_kernel(const float* __restrict__ W_hh)
{
    float* sh_th = smem_dyn;
    float* psum  = smem_dyn + 16 * 1024;

    const int tid = threadIdx.x;
    const int n   = tid & 15;
    const int kc  = tid >> 4;
    const int n0  = blockIdx.x * 16;

    unsigned long long wq[32];
    {
        const ulonglong2* wp =
            (const ulonglong2*)(W_hh + (size_t)(n0 + n) * H_SZ + kc * 64);
#pragma unroll
        for (int t = 0; t < 16; ++t) {
            ulonglong2 u = wp[t];
            wq[2 * t]     = u.x;
            wq[2 * t + 1] = u.y;
        }
    }

    const int rb = tid >> 4;
    const int rn = tid & 15;
    unsigned* barp = &g_bar;

    for (int s = 1; s < S_LEN; ++s) {
        __syncthreads();
        if (tid == 0) {
            __threadfence();
            atomicAdd(barp, 1u);
            const unsigned target = 64u * (unsigned)s;
            unsigned v;
            do {
                asm volatile("ld.acquire.gpu.u32 %0, [%1];" : "=r"(v) : "l"(barp));
            } while (v < target);
        }
        __syncthreads();

        const float xv = g_x[(size_t)s * B_SZ * H_SZ + rb * H_SZ + n0 + rn];

        {
            const float4* src = (const float4*)(g_th + (size_t)(s - 1) * B_SZ * H_SZ);
            float4* dst = (float4*)sh_th;
#pragma unroll
            for (int t = 0; t < 16; ++t)
                dst[tid + 256 * t] = src[tid + 256 * t];
        }
        __syncthreads();

#pragma unroll 1
        for (int b = 0; b < 16; ++b) {
            const ulonglong2* tp = (const ulonglong2*)(sh_th + b * H_SZ + kc * 64);
            unsigned long long s0 = 0ull, s1 = 0ull;
#pragma unroll
            for (int t = 0; t < 16; ++t) {
                ulonglong2 u = tp[t];
                asm("fma.rn.f32x2 %0, %1, %2, %0;" : "+l"(s0) : "l"(wq[2 * t]),     "l"(u.x));
                asm("fma.rn.f32x2 %0, %1, %2, %0;" : "+l"(s1) : "l"(wq[2 * t + 1]), "l"(u.y));
            }
            float p0, p1, p2, p3;
            asm("mov.b64 {%0, %1}, %2;" : "=f"(p0), "=f"(p1) : "l"(s0));
            asm("mov.b64 {%0, %1}, %2;" : "=f"(p2), "=f"(p3) : "l"(s1));
            psum[kc * 256 + b * 16 + n] = (p0 + p1) + (p2 + p3);
        }
        __syncthreads();

        float acc = xv;
#pragma unroll
        for (int k2 = 0; k2 < 16; ++k2)
            acc += psum[k2 * 256 + rb * 16 + rn];
        const size_t oi = (size_t)s * B_SZ * H_SZ + rb * H_SZ + n0 + rn;
        const float v = tanhf(acc);
        g_th[oi] = v;
        split_fp16(v, g_th_hi[oi], g_th_lo[oi]);
    }
}

// ---------------------------------------------------------------------------
// W_out -> fp16 (single precision level; A carries the extra bits)
// ---------------------------------------------------------------------------
__global__ void __launch_bounds__(256) convert_wo_kernel(const float* __restrict__ W_out)
{
    size_t total = (size_t)V_SZ * H_SZ;
    size_t stride = (size_t)gridDim.x * blockDim.x;
    for (size_t i = (size_t)blockIdx.x * blockDim.x + threadIdx.x; i < total; i += stride) {
        g_wo_h[i] = __float2half_rn(W_out[i]);
    }
}

// ---------------------------------------------------------------------------
// HMMA (mma.sync) fp16 2-term output GEMM:
//   C[4096, 32000] = th[4096,1024] @ W_out[32000,1024]^T + b_out
// BM=128, BN=256, BK=64. 8 warps = 2(M) x 4(N); warp tile 64x64.
// D = Ah*B + Al*B  (A split fp16 hi/lo, B single fp16, fp32 accum).
// cp.async double-buffered, SW128-swizzled smem, NON-trans ldmatrix.
// ---------------------------------------------------------------------------
#define KCHUNK    64
#define NKC       (H_SZ / KCHUNK)    // 16
#define BN_TILE   256
#define A_TSZ     (128 * 128)        // 16 KB per A fp16 tile (128r x 64 halves)
#define B_TSZ     (BN_TILE * 128)    // 32 KB B fp16 tile
#define STAGE_SZ  (2 * A_TSZ + B_TSZ)       // 64 KB
#define MMA_SMEM  (1024 + 2 * STAGE_SZ)     // ~129 KB
#define MMA_NT    256

extern __shared__ char smem_raw[];

__device__ __forceinline__ void fill_stage(
    uint32_t sbase, int stage, int kc, int m0, int n0, int tid)
{
    const uint32_t st = sbase + (uint32_t)stage * STAGE_SZ;
    // A: 128 rows x 64 halves = 1024 16B-chunks (4/thread), hi + lo
#pragma unroll
    for (int i = 0; i < 4; ++i) {
        int ch = tid + MMA_NT * i;
        int r = ch >> 3, c = ch & 7;
        uint32_t so = SMEM_SWIZZLE_128B((uint32_t)(r * 128 + c * 16));
        size_t ga = (size_t)(m0 + r) * H_SZ + kc * KCHUNK + c * 8;
        cp16(st + so,         g_th_hi + ga);
        cp16(st + A_TSZ + so, g_th_lo + ga);
    }
    // B: 256 rows x 64 halves = 2048 16B-chunks (8/thread)
#pragma unroll
    for (int i = 0; i < 8; ++i) {
        int ch = tid + MMA_NT * i;
        int r = ch >> 3, c = ch & 7;
        uint32_t so = SMEM_SWIZZLE_128B((uint32_t)(r * 128 + c * 16));
        size_t gb = (size_t)(n0 + r) * H_SZ + kc * KCHUNK + c * 8;
        cp16(st + 2 * A_TSZ + so, g_wo_h + gb);
    }
}

__global__ void __launch_bounds__(MMA_NT, 1) mma_out_kernel(
    const float* __restrict__ b_out, float* __restrict__ C)
{
    const uint32_t sbase = (smem_to_u32(smem_raw) + 1023u) & ~1023u;

    const int tid    = threadIdx.x;
    const int wid    = tid >> 5;
    const int lane   = tid & 31;
    const int warp_m = wid & 1;       // 0..1 -> 64 rows
    const int warp_n = wid >> 1;      // 0..3 -> 64 cols

    const int m0 = blockIdx.y * 128;
    const int n0 = blockIdx.x * BN_TILE;

    // ldmatrix lane address components (NON-trans)
    const int a_row = warp_m * 64 + ((lane >> 3) & 1) * 8 + (lane & 7);
    const int a_kb  = ((lane >> 4) & 1) * 16;
    const int b_lrow = ((lane >> 4) & 1) * 8 + (lane & 7);   // + warp_n*64 + np*16
    const int b_kb   = ((lane >> 3) & 1) * 16;

    float acc[4][8][4];
#pragma unroll
    for (int i = 0; i < 4; i++)
#pragma unroll
        for (int j = 0; j < 8; j++)
#pragma unroll
            for (int k = 0; k < 4; k++) acc[i][j][k] = 0.f;

    fill_stage(sbase, 0, 0, m0, n0, tid);
    cp_commit();

    for (int kc = 0; kc < NKC; ++kc) {
        const int buf = kc & 1;
        if (kc + 1 < NKC) {
            fill_stage(sbase, buf ^ 1, kc + 1, m0, n0, tid);
            cp_commit();
            cp_wait<1>();
        } else {
            cp_wait<0>();
        }
        __syncthreads();

        const uint32_t st   = sbase + (uint32_t)buf * STAGE_SZ;
        const uint32_t stA  = st;
        const uint32_t stAl = st + A_TSZ;
        const uint32_t stB  = st + 2 * A_TSZ;

#pragma unroll
        for (int ks = 0; ks < 4; ++ks) {
            uint32_t ah[4][4], al[4][4];
#pragma unroll
            for (int mt = 0; mt < 4; ++mt) {
                uint32_t off = (uint32_t)((a_row + mt * 16) * 128 + ks * 32 + a_kb);
                uint32_t so  = SMEM_SWIZZLE_128B(off);
                ldsm_x4(ah[mt], stA  + so);
                ldsm_x4(al[mt], stAl + so);
            }
            uint32_t bh[4][4];   // np: 16-col groups; each x4 = 2 n8 frags
#pragma unroll
            for (int np = 0; np < 4; ++np) {
                uint32_t row = (uint32_t)(warp_n * 64 + np * 16 + b_lrow);
                uint32_t off = row * 128 + ks * 32 + b_kb;
                uint32_t so  = SMEM_SWIZZLE_128B(off);
                ldsm_x4(bh[np], stB + so);
            }
#pragma unroll
            for (int mt = 0; mt < 4; ++mt) {
#pragma unroll
                for (int nt = 0; nt < 8; ++nt) {
                    const uint32_t* bf = &bh[nt >> 1][(nt & 1) * 2];
                    mma16816h(acc[mt][nt], ah[mt], bf);
                    mma16816h(acc[mt][nt], al[mt], bf);
                }
            }
        }
        __syncthreads();
    }

    // epilogue
    const int group = lane >> 2;
    const int tig   = lane & 3;
#pragma unroll
    for (int nt = 0; nt < 8; ++nt) {
        const int col = n0 + warp_n * 64 + nt * 8 + tig * 2;
        const float2 bv = *(const float2*)(b_out + col);
#pragma unroll
        for (int mt = 0; mt < 4; ++mt) {
            const int row0 = m0 + warp_m * 64 + mt * 16 + group;
            float2 v0, v1;
            v0.x = acc[mt][nt][0] + bv.x;
            v0.y = acc[mt][nt][1] + bv.y;
            v1.x = acc[mt][nt][2] + bv.x;
            v1.y = acc[mt][nt][3] + bv.y;
            *(float2*)(C + (size_t)row0 * V_SZ + col)       = v0;
            *(float2*)(C + (size_t)(row0 + 8) * V_SZ + col) = v1;
        }
    }
}

// ---------------------------------------------------------------------------
// kernel_launch
// ---------------------------------------------------------------------------
extern "C" void kernel_launch(void* const* d_in, const int* in_sizes, int n_in,
                              void* d_out, int out_size)
{
    (void)in_sizes; (void)n_in; (void)out_size;
    const int*   tokens = (const int*)  d_in[0];
    const float* emb    = (const float*)d_in[1];
    const float* W_in   = (const float*)d_in[2];
    const float* W_hh   = (const float*)d_in[3];
    const float* W_out  = (const float*)d_in[4];
    const float* b_out  = (const float*)d_in[5];
    float* out = (float*)d_out;

    float* gx = nullptr;
    cudaGetSymbolAddress((void**)&gx, g_x);

    // 0) W_out -> fp16
    convert_wo_kernel<<<2048, 256>>>(W_out);

    // 1) x = gather(emb) @ W_in^T
    sgemm128_nt<true><<<dim3(H_SZ / 128, M_SZ / 128), 256>>>(
        emb, W_in, nullptr, tokens, gx, H_SZ, E_SZ);

    // 2) th[0] = tanh(x[0]) + fp16 split; reset barrier
    init_kernel<<<(B_SZ * H_SZ + 255) / 256, 256>>>();

    // 3) persistent recurrence (emits fp32 + fp16 hi/lo)
    const int scan_smem = (16 * 1024 + 16 * 16 * 16) * (int)sizeof(float);
    cudaFuncSetAttribute(rnn_scan_kernel,
                         cudaFuncAttributeMaxDynamicSharedMemorySize, scan_smem);
    rnn_scan_kernel<<<H_SZ / 16, 256, scan_smem>>>(W_hh);

    // 4) logits = th @ W_out^T + b_out via HMMA (fp16 2-term A-split)
    cudaFuncSetAttribute(mma_out_kernel,
                         cudaFuncAttributeMaxDynamicSharedMemorySize, MMA_SMEM);
    mma_out_kernel<<<dim3(V_SZ / BN_TILE, M_SZ / 128), MMA_NT, MMA_SMEM>>>(b_out, out);
}

// round 15
// speedup vs baseline: 1.6006x; 1.2480x over previous
#include <cuda_runtime.h>
#include <cuda_fp16.h>
#include <math.h>
#include <stdint.h>

#define S_LEN 256
#define B_SZ  16
#define V_SZ  32000
#define E_SZ  512
#define H_SZ  1024
#define M_SZ  (S_LEN * B_SZ)   // 4096

// ---------------------------------------------------------------------------
// Device scratch (static — no runtime allocation allowed)
// ---------------------------------------------------------------------------
__device__ float    g_x [M_SZ * H_SZ];
__device__ float    g_th[M_SZ * H_SZ];
__device__ unsigned g_bar;
__device__ __align__(16) __half g_th_h[M_SZ * H_SZ];
__device__ __align__(16) __half g_wo_h[(size_t)V_SZ * H_SZ];

#define SMEM_SWIZZLE_128B(o) ((o) ^ (((o) >> 3) & 0x70))

__device__ __forceinline__ uint32_t smem_to_u32(const void* p) {
    uint32_t a;
    asm("{ .reg .u64 t; cvta.to.shared.u64 t, %1; cvt.u32.u64 %0, t; }"
        : "=r"(a) : "l"(p));
    return a;
}

__device__ __forceinline__ void cp16(uint32_t saddr, const void* g) {
    unsigned long long ga = (unsigned long long)__cvta_generic_to_global(g);
    asm volatile("cp.async.cg.shared.global [%0], [%1], 16;"
                 :: "r"(saddr), "l"(ga) : "memory");
}
__device__ __forceinline__ void cp_commit() {
    asm volatile("cp.async.commit_group;" ::: "memory");
}
template<int N>
__device__ __forceinline__ void cp_wait() {
    asm volatile("cp.async.wait_group %0;" :: "n"(N) : "memory");
}

__device__ __forceinline__ void ldsm_x4(uint32_t* r, uint32_t addr) {
    asm volatile("ldmatrix.sync.aligned.m8n8.x4.shared.b16 {%0,%1,%2,%3}, [%4];"
                 : "=r"(r[0]), "=r"(r[1]), "=r"(r[2]), "=r"(r[3]) : "r"(addr));
}
__device__ __forceinline__ void mma16816h(float* d, const uint32_t* a, const uint32_t* b) {
    asm volatile(
        "mma.sync.aligned.m16n8k16.row.col.f32.f16.f16.f32 "
        "{%0,%1,%2,%3}, {%4,%5,%6,%7}, {%8,%9}, {%0,%1,%2,%3};"
        : "+f"(d[0]), "+f"(d[1]), "+f"(d[2]), "+f"(d[3])
        : "r"(a[0]), "r"(a[1]), "r"(a[2]), "r"(a[3]), "r"(b[0]), "r"(b[1]));
}

// ---------------------------------------------------------------------------
// Scalar NT SGEMM (f32x2) — input projection only (M=4096,N=1024,K=512)
// ---------------------------------------------------------------------------
template<bool GATHER>
__global__ void __launch_bounds__(256) sgemm128_nt(
    const float* __restrict__ A,
    const float* __restrict__ B,
    const float* __restrict__ bias,
    const int*   __restrict__ tokens,
    float* __restrict__ C,
    int N, int K)
{
    __shared__ float As[2][8][128];
    __shared__ float Bs[2][8][128];

    const int tid = threadIdx.x;
    const int bm  = blockIdx.y;
    const int bn  = blockIdx.x;

    const int lrow = tid >> 1;
    const int lk   = (tid & 1) << 2;

    const float* Arow;
    if (GATHER) {
        const int tok = tokens[bm * 128 + lrow];
        Arow = A + (size_t)tok * K;
    } else {
        Arow = A + (size_t)(bm * 128 + lrow) * K;
    }
    const float* Brow = B + (size_t)(bn * 128 + lrow) * K;

    const int tx = tid & 15;
    const int ty = tid >> 4;

    unsigned long long acc2[8][4];
#pragma unroll
    for (int i = 0; i < 8; i++)
#pragma unroll
        for (int jp = 0; jp < 4; jp++) acc2[i][jp] = 0ull;

    {
        float4 a4 = *(const float4*)(Arow + lk);
        float4 b4 = *(const float4*)(Brow + lk);
        As[0][lk + 0][lrow] = a4.x; As[0][lk + 1][lrow] = a4.y;
        As[0][lk + 2][lrow] = a4.z; As[0][lk + 3][lrow] = a4.w;
        Bs[0][lk + 0][lrow] = b4.x; Bs[0][lk + 1][lrow] = b4.y;
        Bs[0][lk + 2][lrow] = b4.z; Bs[0][lk + 3][lrow] = b4.w;
    }
    __syncthreads();

    const int nt = K >> 3;
    for (int t = 0; t < nt; ++t) {
        const int cur = t & 1;
        float4 na, nb;
        if (t + 1 < nt) {
            na = *(const float4*)(Arow + (t + 1) * 8 + lk);
            nb = *(const float4*)(Brow + (t + 1) * 8 + lk);
        }
#pragma unroll
        for (int k = 0; k < 8; k++) {
            float af[8];
            *(float4*)(af)     = *(const float4*)&As[cur][k][ty * 8];
            *(float4*)(af + 4) = *(const float4*)&As[cur][k][ty * 8 + 4];
            ulonglong2 b01 = *(const ulonglong2*)&Bs[cur][k][tx * 8];
            ulonglong2 b23 = *(const ulonglong2*)&Bs[cur][k][tx * 8 + 4];
#pragma unroll
            for (int i = 0; i < 8; i++) {
                unsigned long long ai;
                asm("mov.b64 %0, {%1, %1};" : "=l"(ai) : "f"(af[i]));
                asm("fma.rn.f32x2 %0, %1, %2, %0;" : "+l"(acc2[i][0]) : "l"(ai), "l"(b01.x));
                asm("fma.rn.f32x2 %0, %1, %2, %0;" : "+l"(acc2[i][1]) : "l"(ai), "l"(b01.y));
                asm("fma.rn.f32x2 %0, %1, %2, %0;" : "+l"(acc2[i][2]) : "l"(ai), "l"(b23.x));
                asm("fma.rn.f32x2 %0, %1, %2, %0;" : "+l"(acc2[i][3]) : "l"(ai), "l"(b23.y));
            }
        }
        if (t + 1 < nt) {
            const int nxt = cur ^ 1;
            As[nxt][lk + 0][lrow] = na.x; As[nxt][lk + 1][lrow] = na.y;
            As[nxt][lk + 2][lrow] = na.z; As[nxt][lk + 3][lrow] = na.w;
            Bs[nxt][lk + 0][lrow] = nb.x; Bs[nxt][lk + 1][lrow] = nb.y;
            Bs[nxt][lk + 2][lrow] = nb.z; Bs[nxt][lk + 3][lrow] = nb.w;
            __syncthreads();
        }
    }

    const int gm0 = bm * 128 + ty * 8;
    const int gn0 = bn * 128 + tx * 8;
    float bb[8];
    if (bias) {
        *(float4*)(bb)     = *(const float4*)(bias + gn0);
        *(float4*)(bb + 4) = *(const float4*)(bias + gn0 + 4);
    } else {
#pragma unroll
        for (int j = 0; j < 8; j++) bb[j] = 0.f;
    }
#pragma unroll
    for (int i = 0; i < 8; i++) {
        float cv[8];
#pragma unroll
        for (int jp = 0; jp < 4; jp++) {
            float lo, hi;
            asm("mov.b64 {%0, %1}, %2;" : "=f"(lo), "=f"(hi) : "l"(acc2[i][jp]));
            cv[2 * jp]     = lo + bb[2 * jp];
            cv[2 * jp + 1] = hi + bb[2 * jp + 1];
        }
        float* crow = C + (size_t)(gm0 + i) * N + gn0;
        *(float4*)(crow)     = *(float4*)(cv);
        *(float4*)(crow + 4) = *(float4*)(cv + 4);
    }
}

// ---------------------------------------------------------------------------
// init: th[0] = tanh(x[0]) (+ fp16); reset grid barrier
// ---------------------------------------------------------------------------
__global__ void __launch_bounds__(256) init_kernel()
{
    int i = blockIdx.x * blockDim.x + threadIdx.x;
    if (i < B_SZ * H_SZ) {
        float v = tanhf(g_x[i]);
        g_th[i] = v;
        g_th_h[i] = __float2half_rn(v);
    }
    if (i == 0) g_bar = 0u;
}

// ---------------------------------------------------------------------------
// Persistent recurrence scan; emits fp32 th and fp16 th.
// ---------------------------------------------------------------------------
extern __shared__ float smem_dyn[];

__global__ void __launch_bounds__(256) rnn_scan_kernel(const float* __restrict__ W_hh)
{
    float* sh_th = smem_dyn;
    float* psum  = smem_dyn + 16 * 1024;

    const int tid = threadIdx.x;
    const int n   = tid & 15;
    const int kc  = tid >> 4;
    const int n0  = blockIdx.x * 16;

    unsigned long long wq[32];
    {
        const ulonglong2* wp =
            (const ulonglong2*)(W_hh + (size_t)(n0 + n) * H_SZ + kc * 64);
#pragma unroll
        for (int t = 0; t < 16; ++t) {
            ulonglong2 u = wp[t];
            wq[2 * t]     = u.x;
            wq[2 * t + 1] = u.y;
        }
    }

    const int rb = tid >> 4;
    const int rn = tid & 15;
    unsigned* barp = &g_bar;

    for (int s = 1; s < S_LEN; ++s) {
        __syncthreads();
        if (tid == 0) {
            __threadfence();
            atomicAdd(barp, 1u);
            const unsigned target = 64u * (unsigned)s;
            unsigned v;
            do {
                asm volatile("ld.acquire.gpu.u32 %0, [%1];" : "=r"(v) : "l"(barp));
            } while (v < target);
        }
        __syncthreads();

        const float xv = g_x[(size_t)s * B_SZ * H_SZ + rb * H_SZ + n0 + rn];

        {
            const float4* src = (const float4*)(g_th + (size_t)(s - 1) * B_SZ * H_SZ);
            float4* dst = (float4*)sh_th;
#pragma unroll
            for (int t = 0; t < 16; ++t)
                dst[tid + 256 * t] = src[tid + 256 * t];
        }
        __syncthreads();

#pragma unroll 1
        for (int b = 0; b < 16; ++b) {
            const ulonglong2* tp = (const ulonglong2*)(sh_th + b * H_SZ + kc * 64);
            unsigned long long s0 = 0ull, s1 = 0ull;
#pragma unroll
            for (int t = 0; t < 16; ++t) {
                ulonglong2 u = tp[t];
                asm("fma.rn.f32x2 %0, %1, %2, %0;" : "+l"(s0) : "l"(wq[2 * t]),     "l"(u.x));
                asm("fma.rn.f32x2 %0, %1, %2, %0;" : "+l"(s1) : "l"(wq[2 * t + 1]), "l"(u.y));
            }
            float p0, p1, p2, p3;
            asm("mov.b64 {%0, %1}, %2;" : "=f"(p0), "=f"(p1) : "l"(s0));
            asm("mov.b64 {%0, %1}, %2;" : "=f"(p2), "=f"(p3) : "l"(s1));
            psum[kc * 256 + b * 16 + n] = (p0 + p1) + (p2 + p3);
        }
        __syncthreads();

        float acc = xv;
#pragma unroll
        for (int k2 = 0; k2 < 16; ++k2)
            acc += psum[k2 * 256 + rb * 16 + rn];
        const size_t oi = (size_t)s * B_SZ * H_SZ + rb * H_SZ + n0 + rn;
        const float v = tanhf(acc);
        g_th[oi] = v;
        g_th_h[oi] = __float2half_rn(v);
    }
}

// ---------------------------------------------------------------------------
// W_out -> fp16
// ---------------------------------------------------------------------------
__global__ void __launch_bounds__(256) convert_wo_kernel(const float* __restrict__ W_out)
{
    size_t total = (size_t)V_SZ * H_SZ;
    size_t stride = (size_t)gridDim.x * blockDim.x;
    for (size_t i = (size_t)blockIdx.x * blockDim.x + threadIdx.x; i < total; i += stride) {
        g_wo_h[i] = __float2half_rn(W_out[i]);
    }
}

// ---------------------------------------------------------------------------
// HMMA (mma.sync) fp16 single-term output GEMM:
//   C[4096, 32000] = th[4096,1024] @ W_out[32000,1024]^T + b_out
// BM=128, BN=256, BK=64. 8 warps = 2(M) x 4(N); warp tile 64x64.
// D = A*B (both fp16, fp32 accum). Error budget: ~sqrt(2) x the measured
// 2.07e-4 of the B-only rounding = ~2.9e-4 << 1e-3.
// cp.async double-buffered, SW128-swizzled smem, NON-trans ldmatrix.
// ---------------------------------------------------------------------------
#define KCHUNK    64
#define NKC       (H_SZ / KCHUNK)    // 16
#define BN_TILE   256
#define A_TSZ     (128 * 128)        // 16 KB A fp16 tile (128r x 64 halves)
#define B_TSZ     (BN_TILE * 128)    // 32 KB B fp16 tile
#define STAGE_SZ  (A_TSZ + B_TSZ)           // 48 KB
#define MMA_SMEM  (1024 + 2 * STAGE_SZ)     // ~97 KB
#define MMA_NT    256

extern __shared__ char smem_raw[];

__device__ __forceinline__ void fill_stage(
    uint32_t sbase, int stage, int kc, int m0, int n0, int tid)
{
    const uint32_t st = sbase + (uint32_t)stage * STAGE_SZ;
    // A: 128 rows x 64 halves = 1024 16B-chunks (4/thread)
#pragma unroll
    for (int i = 0; i < 4; ++i) {
        int ch = tid + MMA_NT * i;
        int r = ch >> 3, c = ch & 7;
        uint32_t so = SMEM_SWIZZLE_128B((uint32_t)(r * 128 + c * 16));
        size_t ga = (size_t)(m0 + r) * H_SZ + kc * KCHUNK + c * 8;
        cp16(st + so, g_th_h + ga);
    }
    // B: 256 rows x 64 halves = 2048 16B-chunks (8/thread)
#pragma unroll
    for (int i = 0; i < 8; ++i) {
        int ch = tid + MMA_NT * i;
        int r = ch >> 3, c = ch & 7;
        uint32_t so = SMEM_SWIZZLE_128B((uint32_t)(r * 128 + c * 16));
        size_t gb = (size_t)(n0 + r) * H_SZ + kc * KCHUNK + c * 8;
        cp16(st + A_TSZ + so, g_wo_h + gb);
    }
}

__global__ void __launch_bounds__(MMA_NT, 1) mma_out_kernel(
    const float* __restrict__ b_out, float* __restrict__ C)
{
    const uint32_t sbase = (smem_to_u32(smem_raw) + 1023u) & ~1023u;

    const int tid    = threadIdx.x;
    const int wid    = tid >> 5;
    const int lane   = tid & 31;
    const int warp_m = wid & 1;       // 0..1 -> 64 rows
    const int warp_n = wid >> 1;      // 0..3 -> 64 cols

    const int m0 = blockIdx.y * 128;
    const int n0 = blockIdx.x * BN_TILE;

    // ldmatrix lane address components (NON-trans)
    const int a_row = warp_m * 64 + ((lane >> 3) & 1) * 8 + (lane & 7);
    const int a_kb  = ((lane >> 4) & 1) * 16;
    const int b_lrow = ((lane >> 4) & 1) * 8 + (lane & 7);   // + warp_n*64 + np*16
    const int b_kb   = ((lane >> 3) & 1) * 16;

    float acc[4][8][4];
#pragma unroll
    for (int i = 0; i < 4; i++)
#pragma unroll
        for (int j = 0; j < 8; j++)
#pragma unroll
            for (int k = 0; k < 4; k++) acc[i][j][k] = 0.f;

    fill_stage(sbase, 0, 0, m0, n0, tid);
    cp_commit();

    for (int kc = 0; kc < NKC; ++kc) {
        const int buf = kc & 1;
        if (kc + 1 < NKC) {
            fill_stage(sbase, buf ^ 1, kc + 1, m0, n0, tid);
            cp_commit();
            cp_wait<1>();
        } else {
            cp_wait<0>();
        }
        __syncthreads();

        const uint32_t st  = sbase + (uint32_t)buf * STAGE_SZ;
        const uint32_t stA = st;
        const uint32_t stB = st + A_TSZ;

#pragma unroll
        for (int ks = 0; ks < 4; ++ks) {
            uint32_t ah[4][4];
#pragma unroll
            for (int mt = 0; mt < 4; ++mt) {
                uint32_t off = (uint32_t)((a_row + mt * 16) * 128 + ks * 32 + a_kb);
                uint32_t so  = SMEM_SWIZZLE_128B(off);
                ldsm_x4(ah[mt], stA + so);
            }
            uint32_t bh[4][4];   // np: 16-col groups; each x4 = 2 n8 frags
#pragma unroll
            for (int np = 0; np < 4; ++np) {
                uint32_t row = (uint32_t)(warp_n * 64 + np * 16 + b_lrow);
                uint32_t off = row * 128 + ks * 32 + b_kb;
                uint32_t so  = SMEM_SWIZZLE_128B(off);
                ldsm_x4(bh[np], stB + so);
            }
#pragma unroll
            for (int mt = 0; mt < 4; ++mt) {
#pragma unroll
                for (int nt = 0; nt < 8; ++nt) {
                    const uint32_t* bf = &bh[nt >> 1][(nt & 1) * 2];
                    mma16816h(acc[mt][nt], ah[mt], bf);
                }
            }
        }
        __syncthreads();
    }

    // epilogue
    const int group = lane >> 2;
    const int tig   = lane & 3;
#pragma unroll
    for (int nt = 0; nt < 8; ++nt) {
        const int col = n0 + warp_n * 64 + nt * 8 + tig * 2;
        const float2 bv = *(const float2*)(b_out + col);
#pragma unroll
        for (int mt = 0; mt < 4; ++mt) {
            const int row0 = m0 + warp_m * 64 + mt * 16 + group;
            float2 v0, v1;
            v0.x = acc[mt][nt][0] + bv.x;
            v0.y = acc[mt][nt][1] + bv.y;
            v1.x = acc[mt][nt][2] + bv.x;
            v1.y = acc[mt][nt][3] + bv.y;
            *(float2*)(C + (size_t)row0 * V_SZ + col)       = v0;
            *(float2*)(C + (size_t)(row0 + 8) * V_SZ + col) = v1;
        }
    }
}

// ---------------------------------------------------------------------------
// kernel_launch
// ---------------------------------------------------------------------------
extern "C" void kernel_launch(void* const* d_in, const int* in_sizes, int n_in,
                              void* d_out, int out_size)
{
    (void)in_sizes; (void)n_in; (void)out_size;
    const int*   tokens = (const int*)  d_in[0];
    const float* emb    = (const float*)d_in[1];
    const float* W_in   = (const float*)d_in[2];
    const float* W_hh   = (const float*)d_in[3];
    const float* W_out  = (const float*)d_in[4];
    const float* b_out  = (const float*)d_in[5];
    float* out = (float*)d_out;

    float* gx = nullptr;
    cudaGetSymbolAddress((void**)&gx, g_x);

    // 0) W_out -> fp16
    convert_wo_kernel<<<2048, 256>>>(W_out);

    // 1) x = gather(emb) @ W_in^T
    sgemm128_nt<true><<<dim3(H_SZ / 128, M_SZ / 128), 256>>>(
        emb, W_in, nullptr, tokens, gx, H_SZ, E_SZ);

    // 2) th[0] = tanh(x[0]) + fp16; reset barrier
    init_kernel<<<(B_SZ * H_SZ + 255) / 256, 256>>>();

    // 3) persistent recurrence (emits fp32 + fp16)
    const int scan_smem = (16 * 1024 + 16 * 16 * 16) * (int)sizeof(float);
    cudaFuncSetAttribute(rnn_scan_kernel,
                         cudaFuncAttributeMaxDynamicSharedMemorySize, scan_smem);
    rnn_scan_kernel<<<H_SZ / 16, 256, scan_smem>>>(W_hh);

    // 4) logits = th @ W_out^T + b_out via HMMA (single-term fp16)
    cudaFuncSetAttribute(mma_out_kernel,
                         cudaFuncAttributeMaxDynamicSharedMemorySize, MMA_SMEM);
    mma_out_kernel<<<dim3(V_SZ / BN_TILE, M_SZ / 128), MMA_NT, MMA_SMEM>>>(b_out, out);
}

// round 16
// speedup vs baseline: 2.1966x; 1.3723x over previous
#include <cuda_runtime.h>
#include <cuda_fp16.h>
#include <math.h>
#include <stdint.h>

#define S_LEN 256
#define B_SZ  16
#define V_SZ  32000
#define E_SZ  512
#define H_SZ  1024
#define M_SZ  (S_LEN * B_SZ)   // 4096

// ---------------------------------------------------------------------------
// Device scratch (static — no runtime allocation allowed)
// ---------------------------------------------------------------------------
__device__ float    g_x [M_SZ * H_SZ];
__device__ float    g_th[M_SZ * H_SZ];
__device__ unsigned g_bar;          // scan progress: 64*(s) arrivals per step; 64*256 = done
__device__ __align__(16) __half g_th_h[M_SZ * H_SZ];
__device__ __align__(16) __half g_wo_h[(size_t)V_SZ * H_SZ];

#define SMEM_SWIZZLE_128B(o) ((o) ^ (((o) >> 3) & 0x70))

__device__ __forceinline__ uint32_t smem_to_u32(const void* p) {
    uint32_t a;
    asm("{ .reg .u64 t; cvta.to.shared.u64 t, %1; cvt.u32.u64 %0, t; }"
        : "=r"(a) : "l"(p));
    return a;
}

__device__ __forceinline__ void cp16(uint32_t saddr, const void* g) {
    unsigned long long ga = (unsigned long long)__cvta_generic_to_global(g);
    asm volatile("cp.async.cg.shared.global [%0], [%1], 16;"
                 :: "r"(saddr), "l"(ga) : "memory");
}
__device__ __forceinline__ void cp_commit() {
    asm volatile("cp.async.commit_group;" ::: "memory");
}
template<int N>
__device__ __forceinline__ void cp_wait() {
    asm volatile("cp.async.wait_group %0;" :: "n"(N) : "memory");
}

__device__ __forceinline__ void ldsm_x4(uint32_t* r, uint32_t addr) {
    asm volatile("ldmatrix.sync.aligned.m8n8.x4.shared.b16 {%0,%1,%2,%3}, [%4];"
                 : "=r"(r[0]), "=r"(r[1]), "=r"(r[2]), "=r"(r[3]) : "r"(addr));
}
__device__ __forceinline__ void mma16816h(float* d, const uint32_t* a, const uint32_t* b) {
    asm volatile(
        "mma.sync.aligned.m16n8k16.row.col.f32.f16.f16.f32 "
        "{%0,%1,%2,%3}, {%4,%5,%6,%7}, {%8,%9}, {%0,%1,%2,%3};"
        : "+f"(d[0]), "+f"(d[1]), "+f"(d[2]), "+f"(d[3])
        : "r"(a[0]), "r"(a[1]), "r"(a[2]), "r"(a[3]), "r"(b[0]), "r"(b[1]));
}

// ---------------------------------------------------------------------------
// Scalar NT SGEMM (f32x2) — input projection (M=4096,N=1024,K=512).
// GATHER variant also fuses init: rows < 16 (s=0) write th0 = tanh(x0) + fp16.
// ---------------------------------------------------------------------------
template<bool GATHER>
__global__ void __launch_bounds__(256) sgemm128_nt(
    const float* __restrict__ A,
    const float* __restrict__ B,
    const float* __restrict__ bias,
    const int*   __restrict__ tokens,
    float* __restrict__ C,
    int N, int K)
{
    __shared__ float As[2][8][128];
    __shared__ float Bs[2][8][128];

    const int tid = threadIdx.x;
    const int bm  = blockIdx.y;
    const int bn  = blockIdx.x;

    const int lrow = tid >> 1;
    const int lk   = (tid & 1) << 2;

    const float* Arow;
    if (GATHER) {
        const int tok = tokens[bm * 128 + lrow];
        Arow = A + (size_t)tok * K;
    } else {
        Arow = A + (size_t)(bm * 128 + lrow) * K;
    }
    const float* Brow = B + (size_t)(bn * 128 + lrow) * K;

    const int tx = tid & 15;
    const int ty = tid >> 4;

    unsigned long long acc2[8][4];
#pragma unroll
    for (int i = 0; i < 8; i++)
#pragma unroll
        for (int jp = 0; jp < 4; jp++) acc2[i][jp] = 0ull;

    {
        float4 a4 = *(const float4*)(Arow + lk);
        float4 b4 = *(const float4*)(Brow + lk);
        As[0][lk + 0][lrow] = a4.x; As[0][lk + 1][lrow] = a4.y;
        As[0][lk + 2][lrow] = a4.z; As[0][lk + 3][lrow] = a4.w;
        Bs[0][lk + 0][lrow] = b4.x; Bs[0][lk + 1][lrow] = b4.y;
        Bs[0][lk + 2][lrow] = b4.z; Bs[0][lk + 3][lrow] = b4.w;
    }
    __syncthreads();

    const int nt = K >> 3;
    for (int t = 0; t < nt; ++t) {
        const int cur = t & 1;
        float4 na, nb;
        if (t + 1 < nt) {
            na = *(const float4*)(Arow + (t + 1) * 8 + lk);
            nb = *(const float4*)(Brow + (t + 1) * 8 + lk);
        }
#pragma unroll
        for (int k = 0; k < 8; k++) {
            float af[8];
            *(float4*)(af)     = *(const float4*)&As[cur][k][ty * 8];
            *(float4*)(af + 4) = *(const float4*)&As[cur][k][ty * 8 + 4];
            ulonglong2 b01 = *(const ulonglong2*)&Bs[cur][k][tx * 8];
            ulonglong2 b23 = *(const ulonglong2*)&Bs[cur][k][tx * 8 + 4];
#pragma unroll
            for (int i = 0; i < 8; i++) {
                unsigned long long ai;
                asm("mov.b64 %0, {%1, %1};" : "=l"(ai) : "f"(af[i]));
                asm("fma.rn.f32x2 %0, %1, %2, %0;" : "+l"(acc2[i][0]) : "l"(ai), "l"(b01.x));
                asm("fma.rn.f32x2 %0, %1, %2, %0;" : "+l"(acc2[i][1]) : "l"(ai), "l"(b01.y));
                asm("fma.rn.f32x2 %0, %1, %2, %0;" : "+l"(acc2[i][2]) : "l"(ai), "l"(b23.x));
                asm("fma.rn.f32x2 %0, %1, %2, %0;" : "+l"(acc2[i][3]) : "l"(ai), "l"(b23.y));
            }
        }
        if (t + 1 < nt) {
            const int nxt = cur ^ 1;
            As[nxt][lk + 0][lrow] = na.x; As[nxt][lk + 1][lrow] = na.y;
            As[nxt][lk + 2][lrow] = na.z; As[nxt][lk + 3][lrow] = na.w;
            Bs[nxt][lk + 0][lrow] = nb.x; Bs[nxt][lk + 1][lrow] = nb.y;
            Bs[nxt][lk + 2][lrow] = nb.z; Bs[nxt][lk + 3][lrow] = nb.w;
            __syncthreads();
        }
    }

    const int gm0 = bm * 128 + ty * 8;
    const int gn0 = bn * 128 + tx * 8;
    float bb[8];
    if (bias) {
        *(float4*)(bb)     = *(const float4*)(bias + gn0);
        *(float4*)(bb + 4) = *(const float4*)(bias + gn0 + 4);
    } else {
#pragma unroll
        for (int j = 0; j < 8; j++) bb[j] = 0.f;
    }
#pragma unroll
    for (int i = 0; i < 8; i++) {
        float cv[8];
#pragma unroll
        for (int jp = 0; jp < 4; jp++) {
            float lo, hi;
            asm("mov.b64 {%0, %1}, %2;" : "=f"(lo), "=f"(hi) : "l"(acc2[i][jp]));
            cv[2 * jp]     = lo + bb[2 * jp];
            cv[2 * jp + 1] = hi + bb[2 * jp + 1];
        }
        const int row = gm0 + i;
        float* crow = C + (size_t)row * N + gn0;
        *(float4*)(crow)     = *(float4*)(cv);
        *(float4*)(crow + 4) = *(float4*)(cv + 4);
        // fused init: s=0 rows also produce th0 = tanh(x0) (+ fp16)
        if (GATHER && row < B_SZ) {
#pragma unroll
            for (int j = 0; j < 8; j++) {
                float v = tanhf(cv[j]);
                g_th  [row * H_SZ + gn0 + j] = v;
                g_th_h[row * H_SZ + gn0 + j] = __float2half_rn(v);
            }
        }
    }
}

// ---------------------------------------------------------------------------
// Persistent recurrence scan; emits fp32 th and fp16 th.
// Publishes progress via g_bar (release); triggers PDL early so the output
// GEMM can launch and overlap on the remaining SMs.
// ---------------------------------------------------------------------------
extern __shared__ float smem_dyn[];

__global__ void __launch_bounds__(256) rnn_scan_kernel(const float* __restrict__ W_hh)
{
    float* sh_th = smem_dyn;
    float* psum  = smem_dyn + 16 * 1024;

    const int tid = threadIdx.x;
    const int n   = tid & 15;
    const int kc  = tid >> 4;
    const int n0  = blockIdx.x * 16;

    unsigned long long wq[32];
    {
        const ulonglong2* wp =
            (const ulonglong2*)(W_hh + (size_t)(n0 + n) * H_SZ + kc * 64);
#pragma unroll
        for (int t = 0; t < 16; ++t) {
            ulonglong2 u = wp[t];
            wq[2 * t]     = u.x;
            wq[2 * t + 1] = u.y;
        }
    }

    // Let the dependent (PDL) mma_out kernel launch now; it self-synchronizes
    // on g_bar progress before touching th data.
#if __CUDA_ARCH__ >= 900
    cudaTriggerProgrammaticLaunchCompletion();
#endif

    const int rb = tid >> 4;
    const int rn = tid & 15;
    unsigned* barp = &g_bar;

    for (int s = 1; s < S_LEN; ++s) {
        __syncthreads();
        if (tid == 0) {
            __threadfence();
            atomicAdd(barp, 1u);
            const unsigned target = 64u * (unsigned)s;
            unsigned v;
            do {
                asm volatile("ld.acquire.gpu.u32 %0, [%1];" : "=r"(v) : "l"(barp));
            } while (v < target);
        }
        __syncthreads();

        const float xv = g_x[(size_t)s * B_SZ * H_SZ + rb * H_SZ + n0 + rn];

        {
            const float4* src = (const float4*)(g_th + (size_t)(s - 1) * B_SZ * H_SZ);
            float4* dst = (float4*)sh_th;
#pragma unroll
            for (int t = 0; t < 16; ++t)
                dst[tid + 256 * t] = src[tid + 256 * t];
        }
        __syncthreads();

#pragma unroll 1
        for (int b = 0; b < 16; ++b) {
            const ulonglong2* tp = (const ulonglong2*)(sh_th + b * H_SZ + kc * 64);
            unsigned long long s0 = 0ull, s1 = 0ull;
#pragma unroll
            for (int t = 0; t < 16; ++t) {
                ulonglong2 u = tp[t];
                asm("fma.rn.f32x2 %0, %1, %2, %0;" : "+l"(s0) : "l"(wq[2 * t]),     "l"(u.x));
                asm("fma.rn.f32x2 %0, %1, %2, %0;" : "+l"(s1) : "l"(wq[2 * t + 1]), "l"(u.y));
            }
            float p0, p1, p2, p3;
            asm("mov.b64 {%0, %1}, %2;" : "=f"(p0), "=f"(p1) : "l"(s0));
            asm("mov.b64 {%0, %1}, %2;" : "=f"(p2), "=f"(p3) : "l"(s1));
            psum[kc * 256 + b * 16 + n] = (p0 + p1) + (p2 + p3);
        }
        __syncthreads();

        float acc = xv;
#pragma unroll
        for (int k2 = 0; k2 < 16; ++k2)
            acc += psum[k2 * 256 + rb * 16 + rn];
        const size_t oi = (size_t)s * B_SZ * H_SZ + rb * H_SZ + n0 + rn;
        const float v = tanhf(acc);
        g_th[oi] = v;
        g_th_h[oi] = __float2half_rn(v);
    }

    // Final arrive: signals th[255] complete (g_bar reaches 64*256).
    __syncthreads();
    if (tid == 0) {
        __threadfence();
        atomicAdd(barp, 1u);
    }
}

// ---------------------------------------------------------------------------
// W_out -> fp16; also resets the scan progress counter (runs before scan).
// ---------------------------------------------------------------------------
__global__ void __launch_bounds__(256) convert_wo_kernel(const float* __restrict__ W_out)
{
    if (blockIdx.x == 0 && threadIdx.x == 0) g_bar = 0u;
    size_t total = (size_t)V_SZ * H_SZ;
    size_t stride = (size_t)gridDim.x * blockDim.x;
    for (size_t i = (size_t)blockIdx.x * blockDim.x + threadIdx.x; i < total; i += stride) {
        g_wo_h[i] = __float2half_rn(W_out[i]);
    }
}

// ---------------------------------------------------------------------------
// HMMA (mma.sync) fp16 single-term output GEMM (PDL-overlapped with scan):
//   C[4096, 32000] = th[4096,1024] @ W_out[32000,1024]^T + b_out
// BM=128, BN=256, BK=64. 8 warps = 2(M) x 4(N); warp tile 64x64.
// Each CTA waits (acquire-poll on g_bar) until its th rows are produced.
// ---------------------------------------------------------------------------
#define KCHUNK    64
#define NKC       (H_SZ / KCHUNK)    // 16
#define BN_TILE   256
#define A_TSZ     (128 * 128)        // 16 KB A fp16 tile (128r x 64 halves)
#define B_TSZ     (BN_TILE * 128)    // 32 KB B fp16 tile
#define STAGE_SZ  (A_TSZ + B_TSZ)           // 48 KB
#define MMA_SMEM  (1024 + 2 * STAGE_SZ)     // ~97 KB
#define MMA_NT    256

extern __shared__ char smem_raw[];

__device__ __forceinline__ void fill_stage(
    uint32_t sbase, int stage, int kc, int m0, int n0, int tid)
{
    const uint32_t st = sbase + (uint32_t)stage * STAGE_SZ;
#pragma unroll
    for (int i = 0; i < 4; ++i) {
        int ch = tid + MMA_NT * i;
        int r = ch >> 3, c = ch & 7;
        uint32_t so = SMEM_SWIZZLE_128B((uint32_t)(r * 128 + c * 16));
        size_t ga = (size_t)(m0 + r) * H_SZ + kc * KCHUNK + c * 8;
        cp16(st + so, g_th_h + ga);
    }
#pragma unroll
    for (int i = 0; i < 8; ++i) {
        int ch = tid + MMA_NT * i;
        int r = ch >> 3, c = ch & 7;
        uint32_t so = SMEM_SWIZZLE_128B((uint32_t)(r * 128 + c * 16));
        size_t gb = (size_t)(n0 + r) * H_SZ + kc * KCHUNK + c * 8;
        cp16(st + A_TSZ + so, g_wo_h + gb);
    }
}

__global__ void __launch_bounds__(MMA_NT, 1) mma_out_kernel(
    const float* __restrict__ b_out, float* __restrict__ C)
{
    const uint32_t sbase = (smem_to_u32(smem_raw) + 1023u) & ~1023u;

    const int tid    = threadIdx.x;
    const int wid    = tid >> 5;
    const int lane   = tid & 31;
    const int warp_m = wid & 1;       // 0..1 -> 64 rows
    const int warp_n = wid >> 1;      // 0..3 -> 64 cols

    const int m0 = blockIdx.y * 128;
    const int n0 = blockIdx.x * BN_TILE;

    // Wait until th rows [m0, m0+128) are published by the scan.
    // th[s] visible  <=>  g_bar >= 64*(s+1).  s_max = m0/16 + 7.
    if (tid == 0) {
        const unsigned target = 64u * (unsigned)((m0 >> 4) + 8);
        unsigned v;
        for (;;) {
            asm volatile("ld.acquire.gpu.u32 %0, [%1];" : "=r"(v) : "l"(&g_bar));
            if (v >= target) break;
            __nanosleep(128);
        }
    }
    __syncthreads();

    // ldmatrix lane address components (NON-trans)
    const int a_row = warp_m * 64 + ((lane >> 3) & 1) * 8 + (lane & 7);
    const int a_kb  = ((lane >> 4) & 1) * 16;
    const int b_lrow = ((lane >> 4) & 1) * 8 + (lane & 7);   // + warp_n*64 + np*16
    const int b_kb   = ((lane >> 3) & 1) * 16;

    float acc[4][8][4];
#pragma unroll
    for (int i = 0; i < 4; i++)
#pragma unroll
        for (int j = 0; j < 8; j++)
#pragma unroll
            for (int k = 0; k < 4; k++) acc[i][j][k] = 0.f;

    fill_stage(sbase, 0, 0, m0, n0, tid);
    cp_commit();

    for (int kc = 0; kc < NKC; ++kc) {
        const int buf = kc & 1;
        if (kc + 1 < NKC) {
            fill_stage(sbase, buf ^ 1, kc + 1, m0, n0, tid);
            cp_commit();
            cp_wait<1>();
        } else {
            cp_wait<0>();
        }
        __syncthreads();

        const uint32_t st  = sbase + (uint32_t)buf * STAGE_SZ;
        const uint32_t stA = st;
        const uint32_t stB = st + A_TSZ;

#pragma unroll
        for (int ks = 0; ks < 4; ++ks) {
            uint32_t ah[4][4];
#pragma unroll
            for (int mt = 0; mt < 4; ++mt) {
                uint32_t off = (uint32_t)((a_row + mt * 16) * 128 + ks * 32 + a_kb);
                uint32_t so  = SMEM_SWIZZLE_128B(off);
                ldsm_x4(ah[mt], stA + so);
            }
            uint32_t bh[4][4];
#pragma unroll
            for (int np = 0; np < 4; ++np) {
                uint32_t row = (uint32_t)(warp_n * 64 + np * 16 + b_lrow);
                uint32_t off = row * 128 + ks * 32 + b_kb;
                uint32_t so  = SMEM_SWIZZLE_128B(off);
                ldsm_x4(bh[np], stB + so);
            }
#pragma unroll
            for (int mt = 0; mt < 4; ++mt) {
#pragma unroll
                for (int nt = 0; nt < 8; ++nt) {
                    const uint32_t* bf = &bh[nt >> 1][(nt & 1) * 2];
                    mma16816h(acc[mt][nt], ah[mt], bf);
                }
            }
        }
        __syncthreads();
    }

    // epilogue
    const int group = lane >> 2;
    const int tig   = lane & 3;
#pragma unroll
    for (int nt = 0; nt < 8; ++nt) {
        const int col = n0 + warp_n * 64 + nt * 8 + tig * 2;
        const float2 bv = *(const float2*)(b_out + col);
#pragma unroll
        for (int mt = 0; mt < 4; ++mt) {
            const int row0 = m0 + warp_m * 64 + mt * 16 + group;
            float2 v0, v1;
            v0.x = acc[mt][nt][0] + bv.x;
            v0.y = acc[mt][nt][1] + bv.y;
            v1.x = acc[mt][nt][2] + bv.x;
            v1.y = acc[mt][nt][3] + bv.y;
            *(float2*)(C + (size_t)row0 * V_SZ + col)       = v0;
            *(float2*)(C + (size_t)(row0 + 8) * V_SZ + col) = v1;
        }
    }
}

// ---------------------------------------------------------------------------
// kernel_launch
// ---------------------------------------------------------------------------
extern "C" void kernel_launch(void* const* d_in, const int* in_sizes, int n_in,
                              void* d_out, int out_size)
{
    (void)in_sizes; (void)n_in; (void)out_size;
    const int*   tokens = (const int*)  d_in[0];
    const float* emb    = (const float*)d_in[1];
    const float* W_in   = (const float*)d_in[2];
    const float* W_hh   = (const float*)d_in[3];
    const float* W_out  = (const float*)d_in[4];
    const float* b_out  = (const float*)d_in[5];
    float* out = (float*)d_out;

    float* gx = nullptr;
    cudaGetSymbolAddress((void**)&gx, g_x);

    // 0) W_out -> fp16; reset scan progress counter
    convert_wo_kernel<<<2048, 256>>>(W_out);

    // 1) x = gather(emb) @ W_in^T  (epilogue fuses th0 init for rows < 16)
    sgemm128_nt<true><<<dim3(H_SZ / 128, M_SZ / 128), 256>>>(
        emb, W_in, nullptr, tokens, gx, H_SZ, E_SZ);

    // 2) persistent recurrence (publishes progress; triggers PDL early)
    const int scan_smem = (16 * 1024 + 16 * 16 * 16) * (int)sizeof(float);
    cudaFuncSetAttribute(rnn_scan_kernel,
                         cudaFuncAttributeMaxDynamicSharedMemorySize, scan_smem);
    rnn_scan_kernel<<<H_SZ / 16, 256, scan_smem>>>(W_hh);

    // 3) logits = th @ W_out^T + b_out via HMMA, launched with PDL so it
    //    overlaps with the scan; CTAs self-sync on g_bar progress.
    cudaFuncSetAttribute(mma_out_kernel,
                         cudaFuncAttributeMaxDynamicSharedMemorySize, MMA_SMEM);
    {
        cudaLaunchConfig_t cfg = {};
        cfg.gridDim  = dim3(V_SZ / BN_TILE, M_SZ / 128);
        cfg.blockDim = dim3(MMA_NT, 1, 1);
        cfg.dynamicSmemBytes = MMA_SMEM;
        cfg.stream = 0;
        cudaLaunchAttribute attrs[1];
        attrs[0].id = cudaLaunchAttributeProgrammaticStreamSerialization;
        attrs[0].val.programmaticStreamSerializationAllowed = 1;
        cfg.attrs = attrs;
        cfg.numAttrs = 1;
        cudaLaunchKernelEx(&cfg, mma_out_kernel, b_out, out);
    }
}

// round 17
// speedup vs baseline: 2.3117x; 1.0524x over previous
#include <cuda_runtime.h>
#include <cuda_fp16.h>
#include <math.h>
#include <stdint.h>

#define S_LEN 256
#define B_SZ  16
#define V_SZ  32000
#define E_SZ  512
#define H_SZ  1024
#define M_SZ  (S_LEN * B_SZ)   // 4096

// ---------------------------------------------------------------------------
// Device scratch (static — no runtime allocation allowed)
// ---------------------------------------------------------------------------
__device__ float    g_x [M_SZ * H_SZ];
__device__ float    g_th[M_SZ * H_SZ];
__device__ unsigned g_bar;          // scan progress counter
__device__ __align__(16) __half g_th_h [M_SZ * H_SZ];
__device__ __align__(16) __half g_wo_h [(size_t)V_SZ * H_SZ];
__device__ __align__(16) __half g_emb_hi[(size_t)V_SZ * E_SZ];
__device__ __align__(16) __half g_emb_lo[(size_t)V_SZ * E_SZ];
__device__ __align__(16) __half g_win_hi[H_SZ * E_SZ];
__device__ __align__(16) __half g_win_lo[H_SZ * E_SZ];

#define SMEM_SWIZZLE_128B(o) ((o) ^ (((o) >> 3) & 0x70))

__device__ __forceinline__ uint32_t smem_to_u32(const void* p) {
    uint32_t a;
    asm("{ .reg .u64 t; cvta.to.shared.u64 t, %1; cvt.u32.u64 %0, t; }"
        : "=r"(a) : "l"(p));
    return a;
}

__device__ __forceinline__ void cp16(uint32_t saddr, const void* g) {
    unsigned long long ga = (unsigned long long)__cvta_generic_to_global(g);
    asm volatile("cp.async.cg.shared.global [%0], [%1], 16;"
                 :: "r"(saddr), "l"(ga) : "memory");
}
__device__ __forceinline__ void cp_commit() {
    asm volatile("cp.async.commit_group;" ::: "memory");
}
template<int N>
__device__ __forceinline__ void cp_wait() {
    asm volatile("cp.async.wait_group %0;" :: "n"(N) : "memory");
}

__device__ __forceinline__ void ldsm_x4(uint32_t* r, uint32_t addr) {
    asm volatile("ldmatrix.sync.aligned.m8n8.x4.shared.b16 {%0,%1,%2,%3}, [%4];"
                 : "=r"(r[0]), "=r"(r[1]), "=r"(r[2]), "=r"(r[3]) : "r"(addr));
}
__device__ __forceinline__ void mma16816h(float* d, const uint32_t* a, const uint32_t* b) {
    asm volatile(
        "mma.sync.aligned.m16n8k16.row.col.f32.f16.f16.f32 "
        "{%0,%1,%2,%3}, {%4,%5,%6,%7}, {%8,%9}, {%0,%1,%2,%3};"
        : "+f"(d[0]), "+f"(d[1]), "+f"(d[2]), "+f"(d[3])
        : "r"(a[0]), "r"(a[1]), "r"(a[2]), "r"(a[3]), "r"(b[0]), "r"(b[1]));
}

__device__ __forceinline__ void split_fp16(float x, __half& hi, __half& lo)
{
    hi = __float2half_rn(x);
    lo = __float2half_rn(x - __half2float(hi));
}

// ---------------------------------------------------------------------------
// convert 1: emb + W_in hi/lo fp16 splits; resets g_bar. Runs first.
// ---------------------------------------------------------------------------
__global__ void __launch_bounds__(256) convert_emb_win_kernel(
    const float* __restrict__ emb, const float* __restrict__ W_in)
{
    if (blockIdx.x == 0 && threadIdx.x == 0) g_bar = 0u;
    const size_t emb_n = (size_t)V_SZ * E_SZ;
    const size_t win_n = (size_t)H_SZ * E_SZ;
    const size_t stride = (size_t)gridDim.x * blockDim.x;
    for (size_t i = (size_t)blockIdx.x * blockDim.x + threadIdx.x; i < emb_n; i += stride) {
        split_fp16(emb[i], g_emb_hi[i], g_emb_lo[i]);
        if (i < win_n)
            split_fp16(W_in[i], g_win_hi[i], g_win_lo[i]);
    }
}

// ---------------------------------------------------------------------------
// convert 2: W_out -> fp16. PDL-overlapped with the scan (independent of it).
// ---------------------------------------------------------------------------
__global__ void __launch_bounds__(256) convert_wo_kernel(const float* __restrict__ W_out)
{
    size_t total = (size_t)V_SZ * H_SZ;
    size_t stride = (size_t)gridDim.x * blockDim.x;
    for (size_t i = (size_t)blockIdx.x * blockDim.x + threadIdx.x; i < total; i += stride) {
        g_wo_h[i] = __float2half_rn(W_out[i]);
    }
}

// ---------------------------------------------------------------------------
// HMMA input GEMM (3-term fp16 split, gathered A):
//   x[4096, 1024] = emb[tokens][:, 0:512] @ W_in[1024, 512]^T
// BM=128, BN=256, BK=64; 8 warps 2x4; warp tile 64x64.
// D = Ah*Bh + Ah*Bl + Al*Bh  (error ~2^-17 — x effectively fp32-exact).
// Epilogue fuses th0 = tanh(x[0]) (+fp16) for rows < 16.
// ---------------------------------------------------------------------------
#define KCHUNK    64
#define BN_TILE   256
#define IN_NKC    (E_SZ / KCHUNK)    // 8
#define IN_A_TSZ  (128 * 128)
#define IN_B_TSZ  (BN_TILE * 128)
#define IN_STAGE  (2 * IN_A_TSZ + 2 * IN_B_TSZ)   // 96 KB
#define IN_SMEM   (1024 + 2 * IN_STAGE)           // ~193 KB
#define MMA_NT    256

extern __shared__ char smem_raw[];

__device__ __forceinline__ void fill_stage_in(
    uint32_t sbase, int stage, int kc, int m0, int n0, int tid,
    const int* __restrict__ tokens)
{
    const uint32_t st = sbase + (uint32_t)stage * IN_STAGE;
#pragma unroll
    for (int i = 0; i < 4; ++i) {
        int ch = tid + MMA_NT * i;
        int r = ch >> 3, c = ch & 7;
        uint32_t so = SMEM_SWIZZLE_128B((uint32_t)(r * 128 + c * 16));
        const int tok = __ldg(tokens + m0 + r);
        size_t ga = (size_t)tok * E_SZ + kc * KCHUNK + c * 8;
        cp16(st + so,            g_emb_hi + ga);
        cp16(st + IN_A_TSZ + so, g_emb_lo + ga);
    }
#pragma unroll
    for (int i = 0; i < 8; ++i) {
        int ch = tid + MMA_NT * i;
        int r = ch >> 3, c = ch & 7;
        uint32_t so = SMEM_SWIZZLE_128B((uint32_t)(r * 128 + c * 16));
        size_t gb = (size_t)(n0 + r) * E_SZ + kc * KCHUNK + c * 8;
        cp16(st + 2 * IN_A_TSZ + so,            g_win_hi + gb);
        cp16(st + 2 * IN_A_TSZ + IN_B_TSZ + so, g_win_lo + gb);
    }
}

__global__ void __launch_bounds__(MMA_NT, 1) mma_in_kernel(
    const int* __restrict__ tokens)
{
    const uint32_t sbase = (smem_to_u32(smem_raw) + 1023u) & ~1023u;

    const int tid    = threadIdx.x;
    const int wid    = tid >> 5;
    const int lane   = tid & 31;
    const int warp_m = wid & 1;
    const int warp_n = wid >> 1;

    const int m0 = blockIdx.y * 128;
    const int n0 = blockIdx.x * BN_TILE;

    const int a_row = warp_m * 64 + ((lane >> 3) & 1) * 8 + (lane & 7);
    const int a_kb  = ((lane >> 4) & 1) * 16;
    const int b_lrow = ((lane >> 4) & 1) * 8 + (lane & 7);
    const int b_kb   = ((lane >> 3) & 1) * 16;

    float acc[4][8][4];
#pragma unroll
    for (int i = 0; i < 4; i++)
#pragma unroll
        for (int j = 0; j < 8; j++)
#pragma unroll
            for (int k = 0; k < 4; k++) acc[i][j][k] = 0.f;

    fill_stage_in(sbase, 0, 0, m0, n0, tid, tokens);
    cp_commit();

    for (int kc = 0; kc < IN_NKC; ++kc) {
        const int buf = kc & 1;
        if (kc + 1 < IN_NKC) {
            fill_stage_in(sbase, buf ^ 1, kc + 1, m0, n0, tid, tokens);
            cp_commit();
            cp_wait<1>();
        } else {
            cp_wait<0>();
        }
        __syncthreads();

        const uint32_t st   = sbase + (uint32_t)buf * IN_STAGE;
        const uint32_t stAh = st;
        const uint32_t stAl = st + IN_A_TSZ;
        const uint32_t stBh = st + 2 * IN_A_TSZ;
        const uint32_t stBl = st + 2 * IN_A_TSZ + IN_B_TSZ;

#pragma unroll
        for (int ks = 0; ks < 4; ++ks) {
            uint32_t ah[4][4], al[4][4];
#pragma unroll
            for (int mt = 0; mt < 4; ++mt) {
                uint32_t off = (uint32_t)((a_row + mt * 16) * 128 + ks * 32 + a_kb);
                uint32_t so  = SMEM_SWIZZLE_128B(off);
                ldsm_x4(ah[mt], stAh + so);
                ldsm_x4(al[mt], stAl + so);
            }
            uint32_t bh[4][4], bl[4][4];
#pragma unroll
            for (int np = 0; np < 4; ++np) {
                uint32_t row = (uint32_t)(warp_n * 64 + np * 16 + b_lrow);
                uint32_t off = row * 128 + ks * 32 + b_kb;
                uint32_t so  = SMEM_SWIZZLE_128B(off);
                ldsm_x4(bh[np], stBh + so);
                ldsm_x4(bl[np], stBl + so);
            }
#pragma unroll
            for (int mt = 0; mt < 4; ++mt) {
#pragma unroll
                for (int nt = 0; nt < 8; ++nt) {
                    const uint32_t* bhf = &bh[nt >> 1][(nt & 1) * 2];
                    const uint32_t* blf = &bl[nt >> 1][(nt & 1) * 2];
                    mma16816h(acc[mt][nt], ah[mt], bhf);
                    mma16816h(acc[mt][nt], ah[mt], blf);
                    mma16816h(acc[mt][nt], al[mt], bhf);
                }
            }
        }
        __syncthreads();
    }

    // epilogue: write x fp32; rows < 16 also produce th0 (+fp16)
    const int group = lane >> 2;
    const int tig   = lane & 3;
#pragma unroll
    for (int nt = 0; nt < 8; ++nt) {
        const int col = n0 + warp_n * 64 + nt * 8 + tig * 2;
#pragma unroll
        for (int mt = 0; mt < 4; ++mt) {
            const int row0 = m0 + warp_m * 64 + mt * 16 + group;
            float2 v0, v1;
            v0.x = acc[mt][nt][0]; v0.y = acc[mt][nt][1];
            v1.x = acc[mt][nt][2]; v1.y = acc[mt][nt][3];
            *(float2*)(g_x + (size_t)row0 * H_SZ + col)       = v0;
            *(float2*)(g_x + (size_t)(row0 + 8) * H_SZ + col) = v1;
            if (row0 < B_SZ) {   // row0 in 0..7, row0+8 in 8..15
                float t0 = tanhf(v0.x), t1 = tanhf(v0.y);
                float t2 = tanhf(v1.x), t3 = tanhf(v1.y);
                g_th[row0 * H_SZ + col]           = t0;
                g_th[row0 * H_SZ + col + 1]       = t1;
                g_th[(row0 + 8) * H_SZ + col]     = t2;
                g_th[(row0 + 8) * H_SZ + col + 1] = t3;
                g_th_h[row0 * H_SZ + col]           = __float2half_rn(t0);
                g_th_h[row0 * H_SZ + col + 1]       = __float2half_rn(t1);
                g_th_h[(row0 + 8) * H_SZ + col]     = __float2half_rn(t2);
                g_th_h[(row0 + 8) * H_SZ + col + 1] = __float2half_rn(t3);
            }
        }
    }
}

// ---------------------------------------------------------------------------
// Persistent recurrence scan; emits fp32 th and fp16 th.
// Publishes progress via g_bar (release); triggers PDL early so downstream
// kernels (convert_wo, then mma_out) overlap on the remaining SMs.
// ---------------------------------------------------------------------------
extern __shared__ float smem_dyn[];

__global__ void __launch_bounds__(256) rnn_scan_kernel(const float* __restrict__ W_hh)
{
    float* sh_th = smem_dyn;
    float* psum  = smem_dyn + 16 * 1024;

    const int tid = threadIdx.x;
    const int n   = tid & 15;
    const int kc  = tid >> 4;
    const int n0  = blockIdx.x * 16;

    unsigned long long wq[32];
    {
        const ulonglong2* wp =
            (const ulonglong2*)(W_hh + (size_t)(n0 + n) * H_SZ + kc * 64);
#pragma unroll
        for (int t = 0; t < 16; ++t) {
            ulonglong2 u = wp[t];
            wq[2 * t]     = u.x;
            wq[2 * t + 1] = u.y;
        }
    }

#if __CUDA_ARCH__ >= 900
    cudaTriggerProgrammaticLaunchCompletion();
#endif

    const int rb = tid >> 4;
    const int rn = tid & 15;
    unsigned* barp = &g_bar;

    for (int s = 1; s < S_LEN; ++s) {
        __syncthreads();
        if (tid == 0) {
            __threadfence();
            atomicAdd(barp, 1u);
            const unsigned target = 64u * (unsigned)s;
            unsigned v;
            do {
                asm volatile("ld.acquire.gpu.u32 %0, [%1];" : "=r"(v) : "l"(barp));
            } while (v < target);
        }
        __syncthreads();

        const float xv = g_x[(size_t)s * B_SZ * H_SZ + rb * H_SZ + n0 + rn];

        {
            const float4* src = (const float4*)(g_th + (size_t)(s - 1) * B_SZ * H_SZ);
            float4* dst = (float4*)sh_th;
#pragma unroll
            for (int t = 0; t < 16; ++t)
                dst[tid + 256 * t] = src[tid + 256 * t];
        }
        __syncthreads();

#pragma unroll 1
        for (int b = 0; b < 16; ++b) {
            const ulonglong2* tp = (const ulonglong2*)(sh_th + b * H_SZ + kc * 64);
            unsigned long long s0 = 0ull, s1 = 0ull;
#pragma unroll
            for (int t = 0; t < 16; ++t) {
                ulonglong2 u = tp[t];
                asm("fma.rn.f32x2 %0, %1, %2, %0;" : "+l"(s0) : "l"(wq[2 * t]),     "l"(u.x));
                asm("fma.rn.f32x2 %0, %1, %2, %0;" : "+l"(s1) : "l"(wq[2 * t + 1]), "l"(u.y));
            }
            float p0, p1, p2, p3;
            asm("mov.b64 {%0, %1}, %2;" : "=f"(p0), "=f"(p1) : "l"(s0));
            asm("mov.b64 {%0, %1}, %2;" : "=f"(p2), "=f"(p3) : "l"(s1));
            psum[kc * 256 + b * 16 + n] = (p0 + p1) + (p2 + p3);
        }
        __syncthreads();

        float acc = xv;
#pragma unroll
        for (int k2 = 0; k2 < 16; ++k2)
            acc += psum[k2 * 256 + rb * 16 + rn];
        const size_t oi = (size_t)s * B_SZ * H_SZ + rb * H_SZ + n0 + rn;
        const float v = tanhf(acc);
        g_th[oi] = v;
        g_th_h[oi] = __float2half_rn(v);
    }

    __syncthreads();
    if (tid == 0) {
        __threadfence();
        atomicAdd(barp, 1u);
    }
}

// ---------------------------------------------------------------------------
// HMMA fp16 single-term output GEMM (PDL-overlapped with scan):
//   C[4096, 32000] = th[4096,1024] @ W_out[32000,1024]^T + b_out
// BM=128, BN=256; 8 warps 2x4; warp tile 64x64. CTAs self-sync on g_bar.
// ---------------------------------------------------------------------------
#define NKC       (H_SZ / KCHUNK)    // 16
#define A_TSZ     (128 * 128)
#define B_TSZ     (BN_TILE * 128)
#define STAGE_SZ  (A_TSZ + B_TSZ)           // 48 KB
#define MMA_SMEM  (1024 + 2 * STAGE_SZ)     // ~97 KB

__device__ __forceinline__ void fill_stage_out(
    uint32_t sbase, int stage, int kc, int m0, int n0, int tid)
{
    const uint32_t st = sbase + (uint32_t)stage * STAGE_SZ;
#pragma unroll
    for (int i = 0; i < 4; ++i) {
        int ch = tid + MMA_NT * i;
        int r = ch >> 3, c = ch & 7;
        uint32_t so = SMEM_SWIZZLE_128B((uint32_t)(r * 128 + c * 16));
        size_t ga = (size_t)(m0 + r) * H_SZ + kc * KCHUNK + c * 8;
        cp16(st + so, g_th_h + ga);
    }
#pragma unroll
    for (int i = 0; i < 8; ++i) {
        int ch = tid + MMA_NT * i;
        int r = ch >> 3, c = ch & 7;
        uint32_t so = SMEM_SWIZZLE_128B((uint32_t)(r * 128 + c * 16));
        size_t gb = (size_t)(n0 + r) * H_SZ + kc * KCHUNK + c * 8;
        cp16(st + A_TSZ + so, g_wo_h + gb);
    }
}

__global__ void __launch_bounds__(MMA_NT, 1) mma_out_kernel(
    const float* __restrict__ b_out, float* __restrict__ C)
{
    const uint32_t sbase = (smem_to_u32(smem_raw) + 1023u) & ~1023u;

    const int tid    = threadIdx.x;
    const int wid    = tid >> 5;
    const int lane   = tid & 31;
    const int warp_m = wid & 1;
    const int warp_n = wid >> 1;

    const int m0 = blockIdx.y * 128;
    const int n0 = blockIdx.x * BN_TILE;

    // Wait until th rows [m0, m0+128) are published (g_bar >= 64*(s_max+1)).
    if (tid == 0) {
        const unsigned target = 64u * (unsigned)((m0 >> 4) + 8);
        unsigned v;
        for (;;) {
            asm volatile("ld.acquire.gpu.u32 %0, [%1];" : "=r"(v) : "l"(&g_bar));
            if (v >= target) break;
            __nanosleep(128);
        }
    }
    __syncthreads();

    const int a_row = warp_m * 64 + ((lane >> 3) & 1) * 8 + (lane & 7);
    const int a_kb  = ((lane >> 4) & 1) * 16;
    const int b_lrow = ((lane >> 4) & 1) * 8 + (lane & 7);
    const int b_kb   = ((lane >> 3) & 1) * 16;

    float acc[4][8][4];
#pragma unroll
    for (int i = 0; i < 4; i++)
#pragma unroll
        for (int j = 0; j < 8; j++)
#pragma unroll
            for (int k = 0; k < 4; k++) acc[i][j][k] = 0.f;

    fill_stage_out(sbase, 0, 0, m0, n0, tid);
    cp_commit();

    for (int kc = 0; kc < NKC; ++kc) {
        const int buf = kc & 1;
        if (kc + 1 < NKC) {
            fill_stage_out(sbase, buf ^ 1, kc + 1, m0, n0, tid);
            cp_commit();
            cp_wait<1>();
        } else {
            cp_wait<0>();
        }
        __syncthreads();

        const uint32_t st  = sbase + (uint32_t)buf * STAGE_SZ;
        const uint32_t stA = st;
        const uint32_t stB = st + A_TSZ;

#pragma unroll
        for (int ks = 0; ks < 4; ++ks) {
            uint32_t ah[4][4];
#pragma unroll
            for (int mt = 0; mt < 4; ++mt) {
                uint32_t off = (uint32_t)((a_row + mt * 16) * 128 + ks * 32 + a_kb);
                uint32_t so  = SMEM_SWIZZLE_128B(off);
                ldsm_x4(ah[mt], stA + so);
            }
            uint32_t bh[4][4];
#pragma unroll
            for (int np = 0; np < 4; ++np) {
                uint32_t row = (uint32_t)(warp_n * 64 + np * 16 + b_lrow);
                uint32_t off = row * 128 + ks * 32 + b_kb;
                uint32_t so  = SMEM_SWIZZLE_128B(off);
                ldsm_x4(bh[np], stB + so);
            }
#pragma unroll
            for (int mt = 0; mt < 4; ++mt) {
#pragma unroll
                for (int nt = 0; nt < 8; ++nt) {
                    const uint32_t* bf = &bh[nt >> 1][(nt & 1) * 2];
                    mma16816h(acc[mt][nt], ah[mt], bf);
                }
            }
        }
        __syncthreads();
    }

    const int group = lane >> 2;
    const int tig   = lane & 3;
#pragma unroll
    for (int nt = 0; nt < 8; ++nt) {
        const int col = n0 + warp_n * 64 + nt * 8 + tig * 2;
        const float2 bv = *(const float2*)(b_out + col);
#pragma unroll
        for (int mt = 0; mt < 4; ++mt) {
            const int row0 = m0 + warp_m * 64 + mt * 16 + group;
            float2 v0, v1;
            v0.x = acc[mt][nt][0] + bv.x;
            v0.y = acc[mt][nt][1] + bv.y;
            v1.x = acc[mt][nt][2] + bv.x;
            v1.y = acc[mt][nt][3] + bv.y;
            *(float2*)(C + (size_t)row0 * V_SZ + col)       = v0;
            *(float2*)(C + (size_t)(row0 + 8) * V_SZ + col) = v1;
        }
    }
}

// ---------------------------------------------------------------------------
// kernel_launch — PDL chain:
//   convert_emb_win -> mma_in -> scan (trigger early)
//     -> convert_wo (PDL: overlaps scan) -> mma_out (PDL: overlaps scan tail)
// ---------------------------------------------------------------------------
extern "C" void kernel_launch(void* const* d_in, const int* in_sizes, int n_in,
                              void* d_out, int out_size)
{
    (void)in_sizes; (void)n_in; (void)out_size;
    const int*   tokens = (const int*)  d_in[0];
    const float* emb    = (const float*)d_in[1];
    const float* W_in   = (const float*)d_in[2];
    const float* W_hh   = (const float*)d_in[3];
    const float* W_out  = (const float*)d_in[4];
    const float* b_out  = (const float*)d_in[5];
    float* out = (float*)d_out;

    // 0) emb + W_in hi/lo fp16 splits (+ g_bar reset)
    convert_emb_win_kernel<<<2048, 256>>>(emb, W_in);

    // 1) x = gather(emb) @ W_in^T via HMMA 3-term (fused th0 init)
    cudaFuncSetAttribute(mma_in_kernel,
                         cudaFuncAttributeMaxDynamicSharedMemorySize, IN_SMEM);
    mma_in_kernel<<<dim3(H_SZ / BN_TILE, M_SZ / 128), MMA_NT, IN_SMEM>>>(tokens);

    // 2) persistent recurrence (publishes progress; triggers PDL early)
    const int scan_smem = (16 * 1024 + 16 * 16 * 16) * (int)sizeof(float);
    cudaFuncSetAttribute(rnn_scan_kernel,
                         cudaFuncAttributeMaxDynamicSharedMemorySize, scan_smem);
    rnn_scan_kernel<<<H_SZ / 16, 256, scan_smem>>>(W_hh);

    // 3) W_out -> fp16, PDL-launched so it overlaps the scan on free SMs
    {
        cudaLaunchConfig_t cfg = {};
        cfg.gridDim  = dim3(2048, 1, 1);
        cfg.blockDim = dim3(256, 1, 1);
        cfg.dynamicSmemBytes = 0;
        cfg.stream = 0;
        cudaLaunchAttribute attrs[1];
        attrs[0].id = cudaLaunchAttributeProgrammaticStreamSerialization;
        attrs[0].val.programmaticStreamSerializationAllowed = 1;
        cfg.attrs = attrs;
        cfg.numAttrs = 1;
        cudaLaunchKernelEx(&cfg, convert_wo_kernel, W_out);
    }

    // 4) logits via HMMA, PDL-launched (overlaps scan tail; self-syncs on g_bar)
    cudaFuncSetAttribute(mma_out_kernel,
                         cudaFuncAttributeMaxDynamicSharedMemorySize, MMA_SMEM);
    {
        cudaLaunchConfig_t cfg = {};
        cfg.gridDim  = dim3(V_SZ / BN_TILE, M_SZ / 128);
        cfg.blockDim = dim3(MMA_NT, 1, 1);
        cfg.dynamicSmemBytes = MMA_SMEM;
        cfg.stream = 0;
        cudaLaunchAttribute attrs[1];
        attrs[0].id = cudaLaunchAttributeProgrammaticStreamSerialization;
        attrs[0].val.programmaticStreamSerializationAllowed = 1;
        cfg.attrs = attrs;
        cfg.numAttrs = 1;
        cudaLaunchKernelEx(&cfg, mma_out_kernel, b_out, out);
    }
}